// round 9
// baseline (speedup 1.0000x reference)
#include <cuda_runtime.h>
#include <cstdint>

// Problem constants
#define BATCH 4
#define CIN   256
#define HDIM  64
#define WDIM  64
#define HW    4096          // 64*64
#define OUTC  256
#define KKPOS 9             // 3x3
#define CKDIM 2304          // CIN * 9
#define NOFF  27            // 3*K*K offset-conv output channels
#define NPIX  (BATCH * HW)  // 16384
#define NCHUNK 8            // channel-split factor for offset conv

// Fused GEMM config (mma.sync m16n8k8 tf32), N-split for 2 CTAs/SM
#define TM 256              // CTA M tile (ALL out channels -> gather single-pass)
#define TN 64               // CTA N tile (pixels)
#define TK 32               // K per pipeline chunk
#define NSTAGE 2
#define KCHUNKS (CKDIM / TK)                  // 72
#define A_FLOATS (TM * TK)                    // 8192 (32 KB)
#define B_FLOATS (TN * TK)                    // 2048 (8 KB)
#define STAGE_FLOATS (A_FLOATS + B_FLOATS)    // 10240 (40 KB)
#define REC_OFF (NSTAGE * STAGE_FLOATS)       // 20480 floats (80 KB)
// records: 576 int4 (2304 floats) + 576 float4 (2304 floats) = 18 KB
#define GEMM_SMEM_BYTES ((REC_OFF + 2 * 2304) * 4)   // 100352 (98 KB)

__device__ __forceinline__ uint32_t smem_u32(const void* p) {
    uint32_t a;
    asm("{ .reg .u64 t; cvta.to.shared.u64 t, %1; cvt.u32.u64 %0, t; }" : "=r"(a) : "l"(p));
    return a;
}
__device__ __forceinline__ void cp16(uint32_t dst, const void* src) {
    asm volatile("cp.async.cg.shared.global [%0], [%1], 16;" :: "r"(dst), "l"(src));
}
__device__ __forceinline__ float to_tf32(float f) {
    uint32_t u;
    asm("cvt.rna.tf32.f32 %0, %1;" : "=r"(u) : "f"(f));
    return __uint_as_float(u);
}
__device__ __forceinline__ void mma_tf32(float* c, const uint32_t* a, const uint32_t* b) {
    asm volatile(
        "mma.sync.aligned.m16n8k8.row.col.f32.tf32.tf32.f32 "
        "{%0,%1,%2,%3}, {%4,%5,%6,%7}, {%8,%9}, {%0,%1,%2,%3};"
        : "+f"(c[0]), "+f"(c[1]), "+f"(c[2]), "+f"(c[3])
        : "r"(a[0]), "r"(a[1]), "r"(a[2]), "r"(a[3]), "r"(b[0]), "r"(b[1]));
}

// ---------------------------------------------------------------------------
// Scratch (static __device__ arrays: allocation inside kernel_launch is banned)
// ---------------------------------------------------------------------------
__device__ float g_off_part[NCHUNK * NOFF * NPIX];   // 14.2 MB
__device__ int4   g_rec_idx[BATCH * KKPOS * HW];     // 2.36 MB
__device__ float4 g_rec_w  [BATCH * KKPOS * HW];     // 2.36 MB
__device__ float  g_wt[OUTC * CKDIM];                // 2.36 MB (tf32-rounded)

// ---------------------------------------------------------------------------
// Kernel 0: round GEMM weight to tf32 once per launch.
// ---------------------------------------------------------------------------
__global__ __launch_bounds__(256)
void wprep_kernel(const float* __restrict__ weight)
{
    int i = blockIdx.x * 256 + threadIdx.x;
    if (i < OUTC * CKDIM) g_wt[i] = to_tf32(weight[i]);
}

// ---------------------------------------------------------------------------
// Kernel 1a: offset conv partials. grid=(NPIX/128, NCHUNK).
// ---------------------------------------------------------------------------
__global__ __launch_bounds__(128)
void offset_part_kernel(const float* __restrict__ x,
                        const float* __restrict__ w_off)
{
    __shared__ float s_w[NOFF * 16 * KKPOS];

    const int gid = blockIdx.x * blockDim.x + threadIdx.x;
    const int b  = gid >> 12;
    const int hw = gid & 4095;
    const int y  = hw >> 6;
    const int xw = hw & 63;
    const int cbase = blockIdx.y * (CIN / NCHUNK);

    float acc[NOFF];
#pragma unroll
    for (int i = 0; i < NOFF; i++) acc[i] = 0.f;

    const float* xb = x + (size_t)b * CIN * HW;

    for (int sub = 0; sub < 2; sub++) {
        const int c0 = cbase + sub * 16;
        __syncthreads();
        for (int i = threadIdx.x; i < NOFF * 16 * KKPOS; i += blockDim.x) {
            int oc  = i / (16 * KKPOS);
            int rem = i - oc * (16 * KKPOS);
            s_w[i] = w_off[oc * (CIN * KKPOS) + c0 * KKPOS + rem];
        }
        __syncthreads();

        for (int cc = 0; cc < 16; cc++) {
            const float* xp = xb + (size_t)(c0 + cc) * HW;
            float v[9];
#pragma unroll
            for (int j = 0; j < 9; j++) {
                int dy = j / 3 - 1, dx = j % 3 - 1;
                int yy = y + dy, xx = xw + dx;
                v[j] = (yy >= 0 && yy < HDIM && xx >= 0 && xx < WDIM)
                         ? xp[yy * WDIM + xx] : 0.f;
            }
            const float* sw = &s_w[cc * KKPOS];
#pragma unroll
            for (int oc = 0; oc < NOFF; oc++) {
                float s = 0.f;
#pragma unroll
                for (int j = 0; j < 9; j++)
                    s += sw[oc * (16 * KKPOS) + j] * v[j];
                acc[oc] += s;
            }
        }
    }

#pragma unroll
    for (int oc = 0; oc < NOFF; oc++)
        g_off_part[(blockIdx.y * NOFF + oc) * NPIX + gid] = acc[oc];
}

// ---------------------------------------------------------------------------
// Kernel 1b: reduce partials + build sampling records.
// ---------------------------------------------------------------------------
__global__ __launch_bounds__(256)
void offset_rec_kernel(const float* __restrict__ b_off)
{
    const int gid = blockIdx.x * blockDim.x + threadIdx.x;
    const int b  = gid >> 12;
    const int hw = gid & 4095;
    const int y  = hw >> 6;
    const int xw = hw & 63;

    float acc[NOFF];
#pragma unroll
    for (int oc = 0; oc < NOFF; oc++) {
        float s = b_off[oc];
#pragma unroll
        for (int c = 0; c < NCHUNK; c++)
            s += g_off_part[(c * NOFF + oc) * NPIX + gid];
        acc[oc] = s;
    }

#pragma unroll
    for (int kp = 0; kp < KKPOS; kp++) {
        float dy = acc[2 * kp];
        float dx = acc[2 * kp + 1];
        float mask = 1.f / (1.f + __expf(-acc[18 + kp]));

        float py = (float)(y  - 1 + kp / 3) + dy;
        float px = (float)(xw - 1 + kp % 3) + dx;
        float y0f = floorf(py), x0f = floorf(px);
        float ly = py - y0f,   lx = px - x0f;
        int y0 = (int)y0f, x0 = (int)x0f;

        int4 idx; float4 wv;
        {
            int yy = y0, xx = x0;
            bool ok = (yy >= 0 && yy < HDIM && xx >= 0 && xx < WDIM);
            int yc = min(max(yy, 0), HDIM - 1), xc = min(max(xx, 0), WDIM - 1);
            idx.x = yc * WDIM + xc;
            wv.x = ok ? (1.f - ly) * (1.f - lx) * mask : 0.f;
        }
        {
            int yy = y0, xx = x0 + 1;
            bool ok = (yy >= 0 && yy < HDIM && xx >= 0 && xx < WDIM);
            int yc = min(max(yy, 0), HDIM - 1), xc = min(max(xx, 0), WDIM - 1);
            idx.y = yc * WDIM + xc;
            wv.y = ok ? (1.f - ly) * lx * mask : 0.f;
        }
        {
            int yy = y0 + 1, xx = x0;
            bool ok = (yy >= 0 && yy < HDIM && xx >= 0 && xx < WDIM);
            int yc = min(max(yy, 0), HDIM - 1), xc = min(max(xx, 0), WDIM - 1);
            idx.z = yc * WDIM + xc;
            wv.z = ok ? ly * (1.f - lx) * mask : 0.f;
        }
        {
            int yy = y0 + 1, xx = x0 + 1;
            bool ok = (yy >= 0 && yy < HDIM && xx >= 0 && xx < WDIM);
            int yc = min(max(yy, 0), HDIM - 1), xc = min(max(xx, 0), WDIM - 1);
            idx.w = yc * WDIM + xc;
            wv.w = ok ? ly * lx * mask : 0.f;
        }

        int r = ((b * KKPOS + kp) << 12) + hw;
        g_rec_idx[r] = idx;
        g_rec_w[r]   = wv;
    }
}

// ---------------------------------------------------------------------------
// Kernel 2 (fused): gather + tf32 mma.sync GEMM, N-split, 2 CTAs/SM.
// out[b][o][n] = sum_ck g_wt[o][ck] * val(n, ck) + bias[o]
// CTA: M=256 x N=64 pixels x K=2304, 256 threads (8 warps, 4(M)x2(N) grid,
// warp tile 64x32 — verified mapping). Double-buffered; per iteration:
//   wait A(i) -> sync -> cp.async A(i+1) -> issue gather cell0(i+1)
//   -> MMA ks0,ks1 -> combine/STS cell0, issue cell1 -> MMA ks2,ks3
//   -> combine/STS cell1.
// Cross-CTA overlap (2 resident CTAs) hides the gather/barrier tail.
// ---------------------------------------------------------------------------
__device__ __forceinline__ void fill_A(float* sm, int stage, int chunk, int tid)
{
    const int k0 = chunk * TK;
    uint32_t sa = smem_u32(sm + stage * STAGE_FLOATS);
    // 256 rows x 8 kc = 2048 cp16; 256 threads -> 8 each
#pragma unroll
    for (int it = 0; it < 8; it++) {
        int c = tid + it * 256;
        int m = c >> 3, kc = c & 7;
        cp16(sa + (uint32_t)(kc * TM + m) * 16,
             g_wt + (size_t)m * CKDIM + k0 + kc * 4);
    }
    asm volatile("cp.async.commit_group;" ::: "memory");
}

// Issue the 16 gather loads for one B cell (pixel n, kc chunk of 4 k-values).
__device__ __forceinline__ void gatherB_issue(int k0, int n, int kc,
                                              const float* __restrict__ xb,
                                              const int4* s_idx, float* v)
{
#pragma unroll
    for (int q = 0; q < 4; q++) {
        int ck = k0 + kc * 4 + q;
        int c  = ck / KKPOS;
        int kp = ck - c * KKPOS;
        int4 id = s_idx[kp * TN + n];
        const float* xp = xb + (size_t)c * HW;
        v[q * 4 + 0] = xp[id.x];
        v[q * 4 + 1] = xp[id.y];
        v[q * 4 + 2] = xp[id.z];
        v[q * 4 + 3] = xp[id.w];
    }
}

__device__ __forceinline__ void gatherB_store(float* sb, int k0, int n, int kc,
                                              const float4* s_w, const float* v)
{
    float r[4];
#pragma unroll
    for (int q = 0; q < 4; q++) {
        int ck = k0 + kc * 4 + q;
        int c  = ck / KKPOS;
        int kp = ck - c * KKPOS;
        float4 w = s_w[kp * TN + n];
        r[q] = to_tf32(w.x * v[q * 4 + 0] + w.y * v[q * 4 + 1]
                     + w.z * v[q * 4 + 2] + w.w * v[q * 4 + 3]);
    }
    *(float4*)&sb[(kc * TN + n) * 4] = make_float4(r[0], r[1], r[2], r[3]);
}

__global__ __launch_bounds__(256, 2)
void gemm_fused_kernel(const float* __restrict__ x,
                       const float* __restrict__ bias,
                       float* __restrict__ out)
{
    extern __shared__ float sm[];
    const int tid = threadIdx.x;
    const int wid = tid >> 5;
    const int lid = tid & 31;
    const int g   = lid >> 2;      // group id 0..7
    const int t4  = lid & 3;       // thread-in-group
    const int wm  = wid & 3;       // M quarter (64 rows)
    const int wn  = wid >> 2;      // N half (32 cols)
    const int n0  = blockIdx.x * TN;
    const int b   = n0 >> 12;
    const int hw0 = n0 & 4095;
    const float* xb = x + (size_t)b * CIN * HW;

    int4*   s_idx = (int4*)  (sm + REC_OFF);
    float4* s_w   = (float4*)(sm + REC_OFF + 2304);

    // Preload all 9*64 sampling records for this CTA's pixels.
    for (int i = tid; i < KKPOS * TN; i += 256) {
        int kp = i >> 6, n = i & 63;
        int r  = ((b * KKPOS + kp) << 12) + hw0 + n;
        s_idx[i] = g_rec_idx[r];
        s_w[i]   = g_rec_w[r];
    }
    __syncthreads();

    // This thread's two B cells (fixed across chunks).
    const int cn0 = tid & 63,   ckc0 = tid >> 6;      // kc 0..3
    const int cn1 = cn0,        ckc1 = ckc0 + 4;      // kc 4..7

    float acc[4][4][4];
#pragma unroll
    for (int i = 0; i < 4; i++)
#pragma unroll
        for (int j = 0; j < 4; j++)
#pragma unroll
            for (int q = 0; q < 4; q++) acc[i][j][q] = 0.f;

    // Prologue: chunk 0 fully staged in stage 0.
    {
        float v[16];
        fill_A(sm, 0, 0, tid);
        float* sb = sm + A_FLOATS;
        gatherB_issue(0, cn0, ckc0, xb, s_idx, v);
        gatherB_store(sb, 0, cn0, ckc0, s_w, v);
        gatherB_issue(0, cn1, ckc1, xb, s_idx, v);
        gatherB_store(sb, 0, cn1, ckc1, s_w, v);
    }

    for (int i = 0; i < KCHUNKS; i++) {
        const int s = i & 1;
        asm volatile("cp.async.wait_group 0;" ::: "memory");  // A(i) done
        __syncthreads();   // publishes B(i), frees stage s^1

        const bool pre = (i + 1 < KCHUNKS);
        const int  kn0 = (i + 1) * TK;
        float* sbn = sm + (s ^ 1) * STAGE_FLOATS + A_FLOATS;

        if (pre)
            fill_A(sm, s ^ 1, i + 1, tid);

        float v[16];
        if (pre)
            gatherB_issue(kn0, cn0, ckc0, xb, s_idx, v);   // LDGs in flight

        const uint32_t* Au = (const uint32_t*)(sm + s * STAGE_FLOATS);
        const uint32_t* Bu = Au + A_FLOATS;

        // ---- MMA ks0, ks1 (covers cell-0 gather latency) ----
#pragma unroll
        for (int ks = 0; ks < 2; ks++) {
            const int kc0 = 2 * ks, kc1 = 2 * ks + 1;
            uint32_t af[4][4], bf[4][2];
#pragma unroll
            for (int ii = 0; ii < 4; ii++) {
                int m = wm * 64 + ii * 16 + g;
                af[ii][0] = Au[kc0 * (TM * 4) + m * 4 + t4];
                af[ii][1] = Au[kc0 * (TM * 4) + (m + 8) * 4 + t4];
                af[ii][2] = Au[kc1 * (TM * 4) + m * 4 + t4];
                af[ii][3] = Au[kc1 * (TM * 4) + (m + 8) * 4 + t4];
            }
#pragma unroll
            for (int jj = 0; jj < 4; jj++) {
                int n = wn * 32 + jj * 8 + g;
                bf[jj][0] = Bu[kc0 * (TN * 4) + n * 4 + t4];
                bf[jj][1] = Bu[kc1 * (TN * 4) + n * 4 + t4];
            }
#pragma unroll
            for (int ii = 0; ii < 4; ii++)
#pragma unroll
                for (int jj = 0; jj < 4; jj++)
                    mma_tf32(acc[ii][jj], af[ii], bf[jj]);
        }

        if (pre) {
            gatherB_store(sbn, kn0, cn0, ckc0, s_w, v);    // combine + STS
            gatherB_issue(kn0, cn1, ckc1, xb, s_idx, v);   // cell-1 LDGs
        }

        // ---- MMA ks2, ks3 (covers cell-1 gather latency) ----
#pragma unroll
        for (int ks = 2; ks < 4; ks++) {
            const int kc0 = 2 * ks, kc1 = 2 * ks + 1;
            uint32_t af[4][4], bf[4][2];
#pragma unroll
            for (int ii = 0; ii < 4; ii++) {
                int m = wm * 64 + ii * 16 + g;
                af[ii][0] = Au[kc0 * (TM * 4) + m * 4 + t4];
                af[ii][1] = Au[kc0 * (TM * 4) + (m + 8) * 4 + t4];
                af[ii][2] = Au[kc1 * (TM * 4) + m * 4 + t4];
                af[ii][3] = Au[kc1 * (TM * 4) + (m + 8) * 4 + t4];
            }
#pragma unroll
            for (int jj = 0; jj < 4; jj++) {
                int n = wn * 32 + jj * 8 + g;
                bf[jj][0] = Bu[kc0 * (TN * 4) + n * 4 + t4];
                bf[jj][1] = Bu[kc1 * (TN * 4) + n * 4 + t4];
            }
#pragma unroll
            for (int ii = 0; ii < 4; ii++)
#pragma unroll
                for (int jj = 0; jj < 4; jj++)
                    mma_tf32(acc[ii][jj], af[ii], bf[jj]);
        }

        if (pre)
            gatherB_store(sbn, kn0, cn1, ckc1, s_w, v);
    }

    // Epilogue: add bias, store (pixel block stays within one batch).
#pragma unroll
    for (int ii = 0; ii < 4; ii++) {
        int r0 = wm * 64 + ii * 16 + g;
        float bi0 = bias[r0], bi1 = bias[r0 + 8];
        float* p0 = out + ((size_t)(b * OUTC + r0)) * HW + hw0;
        float* p1 = p0 + (size_t)8 * HW;
#pragma unroll
        for (int jj = 0; jj < 4; jj++) {
            int col = wn * 32 + jj * 8 + 2 * t4;
            float2 v0 = make_float2(acc[ii][jj][0] + bi0, acc[ii][jj][1] + bi0);
            float2 v1 = make_float2(acc[ii][jj][2] + bi1, acc[ii][jj][3] + bi1);
            *(float2*)(p0 + col) = v0;
            *(float2*)(p1 + col) = v1;
        }
    }
}

// ---------------------------------------------------------------------------
// Launch: inputs per metadata order: x, w_off, b_off, weight, bias
// ---------------------------------------------------------------------------
extern "C" void kernel_launch(void* const* d_in, const int* in_sizes, int n_in,
                              void* d_out, int out_size)
{
    const float* x      = (const float*)d_in[0];
    const float* w_off  = (const float*)d_in[1];
    const float* b_off  = (const float*)d_in[2];
    const float* weight = (const float*)d_in[3];
    const float* bias   = (const float*)d_in[4];
    float* out = (float*)d_out;

    cudaFuncSetAttribute(gemm_fused_kernel,
                         cudaFuncAttributeMaxDynamicSharedMemorySize,
                         GEMM_SMEM_BYTES);

    wprep_kernel<<<(OUTC * CKDIM + 255) / 256, 256>>>(weight);

    dim3 pgrid(NPIX / 128, NCHUNK);
    offset_part_kernel<<<pgrid, 128>>>(x, w_off);

    offset_rec_kernel<<<NPIX / 256, 256>>>(b_off);

    gemm_fused_kernel<<<NPIX / TN, 256, GEMM_SMEM_BYTES>>>(x, bias, out);
}

// round 10
// speedup vs baseline: 1.3864x; 1.3864x over previous
#include <cuda_runtime.h>
#include <cstdint>

// Problem constants
#define BATCH 4
#define CIN   256
#define HDIM  64
#define WDIM  64
#define HW    4096          // 64*64
#define OUTC  256
#define KKPOS 9             // 3x3
#define CKDIM 2304          // CIN * 9
#define NOFF  27            // 3*K*K offset-conv output channels
#define NPIX  (BATCH * HW)  // 16384
#define NCHUNK 8            // channel-split factor for offset conv

// Fused GEMM config (mma.sync m16n8k8 tf32) — R5 shape, packed fragments
#define TM 256              // CTA M tile (ALL out channels -> gather single-pass)
#define TN 128              // CTA N tile (pixels)
#define TK 32               // K per pipeline chunk
#define NSTAGE 3
#define KCHUNKS (CKDIM / TK)                  // 72
#define A_FLOATS (TM * TK)                    // 8192 (32 KB)
#define B_FLOATS (TN * TK)                    // 4096 (16 KB)
#define STAGE_FLOATS (A_FLOATS + B_FLOATS)    // 12288 (48 KB)
#define REC_OFF (NSTAGE * STAGE_FLOATS)       // float offset of record area
// record area: 1152 int4 (4608 floats) + 1152 float4 (4608 floats)
#define GEMM_SMEM_BYTES ((REC_OFF + 2 * 4608) * 4)   // 184320

__device__ __forceinline__ uint32_t smem_u32(const void* p) {
    uint32_t a;
    asm("{ .reg .u64 t; cvta.to.shared.u64 t, %1; cvt.u32.u64 %0, t; }" : "=r"(a) : "l"(p));
    return a;
}
__device__ __forceinline__ void cp16(uint32_t dst, const void* src) {
    asm volatile("cp.async.cg.shared.global [%0], [%1], 16;" :: "r"(dst), "l"(src));
}
__device__ __forceinline__ float to_tf32(float f) {
    uint32_t u;
    asm("cvt.rna.tf32.f32 %0, %1;" : "=r"(u) : "f"(f));
    return __uint_as_float(u);
}
__device__ __forceinline__ void mma_tf32s(float* c,
                                          uint32_t a0, uint32_t a1, uint32_t a2, uint32_t a3,
                                          uint32_t b0, uint32_t b1) {
    asm volatile(
        "mma.sync.aligned.m16n8k8.row.col.f32.tf32.tf32.f32 "
        "{%0,%1,%2,%3}, {%4,%5,%6,%7}, {%8,%9}, {%0,%1,%2,%3};"
        : "+f"(c[0]), "+f"(c[1]), "+f"(c[2]), "+f"(c[3])
        : "r"(a0), "r"(a1), "r"(a2), "r"(a3), "r"(b0), "r"(b1));
}

// ---------------------------------------------------------------------------
// Scratch (static __device__ arrays: allocation inside kernel_launch is banned)
// ---------------------------------------------------------------------------
__device__ float g_off_part[NCHUNK * NOFF * NPIX];   // 14.2 MB
__device__ int4   g_rec_idx[BATCH * KKPOS * HW];     // 2.36 MB
__device__ float4 g_rec_w  [BATCH * KKPOS * HW];     // 2.36 MB
// Pre-shuffled tf32 weights, fragment-pair packed:
// g_wt2[((c*4 + ks)*256 + m)*8 + t4*2 + half] = tf32(W[m][c*32 + ks*8 + half*4 + t4])
__device__ float  g_wt2[KCHUNKS * A_FLOATS];         // 2.36 MB

// ---------------------------------------------------------------------------
// Kernel 0: round + shuffle GEMM weight into packed layout.
// ---------------------------------------------------------------------------
__global__ __launch_bounds__(256)
void wprep_kernel(const float* __restrict__ weight)
{
    int i = blockIdx.x * 256 + threadIdx.x;
    if (i >= OUTC * CKDIM) return;
    int half = i & 1;
    int t4   = (i >> 1) & 3;
    int m    = (i >> 3) & 255;
    int ksc  = i >> 11;            // c*4 + ks
    int ks   = ksc & 3;
    int c    = ksc >> 2;
    g_wt2[i] = to_tf32(weight[(size_t)m * CKDIM + c * 32 + ks * 8 + half * 4 + t4]);
}

// ---------------------------------------------------------------------------
// Kernel 1a: offset conv partials. grid=(NPIX/128, NCHUNK). (R5 config)
// ---------------------------------------------------------------------------
__global__ __launch_bounds__(128)
void offset_part_kernel(const float* __restrict__ x,
                        const float* __restrict__ w_off)
{
    __shared__ float s_w[NOFF * 16 * KKPOS];

    const int gid = blockIdx.x * blockDim.x + threadIdx.x;
    const int b  = gid >> 12;
    const int hw = gid & 4095;
    const int y  = hw >> 6;
    const int xw = hw & 63;
    const int cbase = blockIdx.y * (CIN / NCHUNK);

    float acc[NOFF];
#pragma unroll
    for (int i = 0; i < NOFF; i++) acc[i] = 0.f;

    const float* xb = x + (size_t)b * CIN * HW;

    for (int sub = 0; sub < 2; sub++) {
        const int c0 = cbase + sub * 16;
        __syncthreads();
        for (int i = threadIdx.x; i < NOFF * 16 * KKPOS; i += blockDim.x) {
            int oc  = i / (16 * KKPOS);
            int rem = i - oc * (16 * KKPOS);
            s_w[i] = w_off[oc * (CIN * KKPOS) + c0 * KKPOS + rem];
        }
        __syncthreads();

        for (int cc = 0; cc < 16; cc++) {
            const float* xp = xb + (size_t)(c0 + cc) * HW;
            float v[9];
#pragma unroll
            for (int j = 0; j < 9; j++) {
                int dy = j / 3 - 1, dx = j % 3 - 1;
                int yy = y + dy, xx = xw + dx;
                v[j] = (yy >= 0 && yy < HDIM && xx >= 0 && xx < WDIM)
                         ? xp[yy * WDIM + xx] : 0.f;
            }
            const float* sw = &s_w[cc * KKPOS];
#pragma unroll
            for (int oc = 0; oc < NOFF; oc++) {
                float s = 0.f;
#pragma unroll
                for (int j = 0; j < 9; j++)
                    s += sw[oc * (16 * KKPOS) + j] * v[j];
                acc[oc] += s;
            }
        }
    }

#pragma unroll
    for (int oc = 0; oc < NOFF; oc++)
        g_off_part[(blockIdx.y * NOFF + oc) * NPIX + gid] = acc[oc];
}

// ---------------------------------------------------------------------------
// Kernel 1b: reduce partials + build sampling records.
// ---------------------------------------------------------------------------
__global__ __launch_bounds__(256)
void offset_rec_kernel(const float* __restrict__ b_off)
{
    const int gid = blockIdx.x * blockDim.x + threadIdx.x;
    const int b  = gid >> 12;
    const int hw = gid & 4095;
    const int y  = hw >> 6;
    const int xw = hw & 63;

    float acc[NOFF];
#pragma unroll
    for (int oc = 0; oc < NOFF; oc++) {
        float s = b_off[oc];
#pragma unroll
        for (int c = 0; c < NCHUNK; c++)
            s += g_off_part[(c * NOFF + oc) * NPIX + gid];
        acc[oc] = s;
    }

#pragma unroll
    for (int kp = 0; kp < KKPOS; kp++) {
        float dy = acc[2 * kp];
        float dx = acc[2 * kp + 1];
        float mask = 1.f / (1.f + __expf(-acc[18 + kp]));

        float py = (float)(y  - 1 + kp / 3) + dy;
        float px = (float)(xw - 1 + kp % 3) + dx;
        float y0f = floorf(py), x0f = floorf(px);
        float ly = py - y0f,   lx = px - x0f;
        int y0 = (int)y0f, x0 = (int)x0f;

        int4 idx; float4 wv;
        {
            int yy = y0, xx = x0;
            bool ok = (yy >= 0 && yy < HDIM && xx >= 0 && xx < WDIM);
            int yc = min(max(yy, 0), HDIM - 1), xc = min(max(xx, 0), WDIM - 1);
            idx.x = yc * WDIM + xc;
            wv.x = ok ? (1.f - ly) * (1.f - lx) * mask : 0.f;
        }
        {
            int yy = y0, xx = x0 + 1;
            bool ok = (yy >= 0 && yy < HDIM && xx >= 0 && xx < WDIM);
            int yc = min(max(yy, 0), HDIM - 1), xc = min(max(xx, 0), WDIM - 1);
            idx.y = yc * WDIM + xc;
            wv.y = ok ? (1.f - ly) * lx * mask : 0.f;
        }
        {
            int yy = y0 + 1, xx = x0;
            bool ok = (yy >= 0 && yy < HDIM && xx >= 0 && xx < WDIM);
            int yc = min(max(yy, 0), HDIM - 1), xc = min(max(xx, 0), WDIM - 1);
            idx.z = yc * WDIM + xc;
            wv.z = ok ? ly * (1.f - lx) * mask : 0.f;
        }
        {
            int yy = y0 + 1, xx = x0 + 1;
            bool ok = (yy >= 0 && yy < HDIM && xx >= 0 && xx < WDIM);
            int yc = min(max(yy, 0), HDIM - 1), xc = min(max(xx, 0), WDIM - 1);
            idx.w = yc * WDIM + xc;
            wv.w = ok ? ly * lx * mask : 0.f;
        }

        int r = ((b * KKPOS + kp) << 12) + hw;
        g_rec_idx[r] = idx;
        g_rec_w[r]   = wv;
    }
}

// ---------------------------------------------------------------------------
// Kernel 2 (fused): gather + tf32 mma.sync GEMM — R5 structure, packed frags.
// SMEM per stage:
//   A: float2 As2[ks][m][t4]   = (a0, a2) pairs  (32 KB)
//   B: float2 Bs2[ks][n][t4]   = (b0, b1) pairs  (16 KB)
// Consumer fragment fetch: lds.64 only (48 MIO ops/warp/chunk vs 96).
// ---------------------------------------------------------------------------
__device__ __forceinline__ void fill_A(float* sm, int stage, int chunk, int tid)
{
    // g_wt2 chunk block is 32 KB fully contiguous — linear cp.async copy.
    uint32_t sa = smem_u32(sm + stage * STAGE_FLOATS);
    const float* src = g_wt2 + (size_t)chunk * A_FLOATS;
#pragma unroll
    for (int it = 0; it < 4; it++) {
        int c = tid + it * 512;
        cp16(sa + (uint32_t)c * 16, src + c * 4);
    }
    asm volatile("cp.async.commit_group;" ::: "memory");
}

// Each thread fills ONE (n, ks) B cell: 8 k-values, 32 gather loads,
// 2 STS.128 in the packed pair layout.
__device__ __forceinline__ void fill_B(float* sm, int stage, int chunk, int tid,
                                       const float* __restrict__ xb,
                                       const int4* s_idx, const float4* s_w)
{
    const int n  = tid & 127;
    const int ks = tid >> 7;          // 0..3
    const int kb = chunk * TK + ks * 8;
    float r[8];

#pragma unroll
    for (int h = 0; h < 2; h++) {     // two halves of 4 k-values
        float v[16];
#pragma unroll
        for (int j = 0; j < 4; j++) {
            int ck = kb + h * 4 + j;
            int c  = ck / KKPOS;
            int kp = ck - c * KKPOS;
            int4 id = s_idx[kp * TN + n];
            const float* xp = xb + (size_t)c * HW;
            v[j * 4 + 0] = xp[id.x];
            v[j * 4 + 1] = xp[id.y];
            v[j * 4 + 2] = xp[id.z];
            v[j * 4 + 3] = xp[id.w];
        }
#pragma unroll
        for (int j = 0; j < 4; j++) {
            int ck = kb + h * 4 + j;
            int c  = ck / KKPOS;
            int kp = ck - c * KKPOS;
            float4 w = s_w[kp * TN + n];
            r[h * 4 + j] = to_tf32(w.x * v[j * 4 + 0] + w.y * v[j * 4 + 1]
                                 + w.z * v[j * 4 + 2] + w.w * v[j * 4 + 3]);
        }
    }

    // Packed write: float2(b0=r[t4], b1=r[4+t4]) at [ks][n][t4]; t4=0..3
    float* sb = sm + stage * STAGE_FLOATS + A_FLOATS + (ks * TN + n) * 8;
    *(float4*)(sb + 0) = make_float4(r[0], r[4], r[1], r[5]);
    *(float4*)(sb + 4) = make_float4(r[2], r[6], r[3], r[7]);
}

__global__ __launch_bounds__(512, 1)
void gemm_fused_kernel(const float* __restrict__ x,
                       const float* __restrict__ bias,
                       float* __restrict__ out)
{
    extern __shared__ float sm[];
    const int tid = threadIdx.x;
    const int wid = tid >> 5;
    const int lid = tid & 31;
    const int g   = lid >> 2;      // group id 0..7
    const int t4  = lid & 3;       // thread-in-group
    const int wm  = wid & 3;       // M quarter (64 rows)
    const int wn  = wid >> 2;      // N quarter (32 cols)
    const int n0  = blockIdx.x * TN;
    const int b   = n0 >> 12;
    const int hw0 = n0 & 4095;
    const float* xb = x + (size_t)b * CIN * HW;

    int4*   s_idx = (int4*)  (sm + REC_OFF);
    float4* s_w   = (float4*)(sm + REC_OFF + 4608);

    // Preload all 9*128 sampling records for this CTA's pixels.
    for (int i = tid; i < KKPOS * TN; i += 512) {
        int kp = i >> 7, n = i & 127;
        int r  = ((b * KKPOS + kp) << 12) + hw0 + n;
        s_idx[i] = g_rec_idx[r];
        s_w[i]   = g_rec_w[r];
    }
    __syncthreads();

    float acc[4][4][4];
#pragma unroll
    for (int i = 0; i < 4; i++)
#pragma unroll
        for (int j = 0; j < 4; j++)
#pragma unroll
            for (int q = 0; q < 4; q++) acc[i][j][q] = 0.f;

    // Prologue: chunks 0,1 staged.
    for (int pf = 0; pf < 2; pf++) {
        fill_A(sm, pf, pf, tid);
        fill_B(sm, pf, pf, tid, xb, s_idx, s_w);
    }

    for (int i = 0; i < KCHUNKS; i++) {
        const int s = i % NSTAGE;
        if (i == KCHUNKS - 1)
            asm volatile("cp.async.wait_group 0;" ::: "memory");
        else
            asm volatile("cp.async.wait_group 1;" ::: "memory");
        __syncthreads();   // publishes B(i), frees stage (i+2)%NSTAGE

        if (i + 2 < KCHUNKS)
            fill_A(sm, (i + 2) % NSTAGE, i + 2, tid);

        const uint2* Au2 = (const uint2*)(sm + s * STAGE_FLOATS);
        const uint2* Bu2 = (const uint2*)(sm + s * STAGE_FLOATS + A_FLOATS);

#pragma unroll
        for (int ks = 0; ks < 4; ks++) {
            uint2 alo[4], ahi[4], bb[4];
#pragma unroll
            for (int ii = 0; ii < 4; ii++) {
                int m = wm * 64 + ii * 16 + g;
                alo[ii] = Au2[(ks * TM + m) * 4 + t4];
                ahi[ii] = Au2[(ks * TM + m + 8) * 4 + t4];
            }
#pragma unroll
            for (int jj = 0; jj < 4; jj++) {
                int n = wn * 32 + jj * 8 + g;
                bb[jj] = Bu2[(ks * TN + n) * 4 + t4];
            }
#pragma unroll
            for (int ii = 0; ii < 4; ii++)
#pragma unroll
                for (int jj = 0; jj < 4; jj++)
                    mma_tf32s(acc[ii][jj],
                              alo[ii].x, ahi[ii].x, alo[ii].y, ahi[ii].y,
                              bb[jj].x, bb[jj].y);
        }

        // Produce B(i+2) into the freed stage; next iter's sync publishes it.
        if (i + 2 < KCHUNKS)
            fill_B(sm, (i + 2) % NSTAGE, i + 2, tid, xb, s_idx, s_w);
    }

    // Epilogue: add bias, store (pixel block stays within one batch).
#pragma unroll
    for (int ii = 0; ii < 4; ii++) {
        int r0 = wm * 64 + ii * 16 + g;
        float bi0 = bias[r0], bi1 = bias[r0 + 8];
        float* p0 = out + ((size_t)(b * OUTC + r0)) * HW + hw0;
        float* p1 = p0 + (size_t)8 * HW;
#pragma unroll
        for (int jj = 0; jj < 4; jj++) {
            int col = wn * 32 + jj * 8 + 2 * t4;
            float2 v0 = make_float2(acc[ii][jj][0] + bi0, acc[ii][jj][1] + bi0);
            float2 v1 = make_float2(acc[ii][jj][2] + bi1, acc[ii][jj][3] + bi1);
            *(float2*)(p0 + col) = v0;
            *(float2*)(p1 + col) = v1;
        }
    }
}

// ---------------------------------------------------------------------------
// Launch: inputs per metadata order: x, w_off, b_off, weight, bias
// ---------------------------------------------------------------------------
extern "C" void kernel_launch(void* const* d_in, const int* in_sizes, int n_in,
                              void* d_out, int out_size)
{
    const float* x      = (const float*)d_in[0];
    const float* w_off  = (const float*)d_in[1];
    const float* b_off  = (const float*)d_in[2];
    const float* weight = (const float*)d_in[3];
    const float* bias   = (const float*)d_in[4];
    float* out = (float*)d_out;

    cudaFuncSetAttribute(gemm_fused_kernel,
                         cudaFuncAttributeMaxDynamicSharedMemorySize,
                         GEMM_SMEM_BYTES);

    wprep_kernel<<<(OUTC * CKDIM + 255) / 256, 256>>>(weight);

    dim3 pgrid(NPIX / 128, NCHUNK);
    offset_part_kernel<<<pgrid, 128>>>(x, w_off);

    offset_rec_kernel<<<NPIX / 256, 256>>>(b_off);

    gemm_fused_kernel<<<NPIX / TN, 512, GEMM_SMEM_BYTES>>>(x, bias, out);
}

// round 11
// speedup vs baseline: 1.5683x; 1.1312x over previous
#include <cuda_runtime.h>
#include <cstdint>

// Problem constants
#define BATCH 4
#define CIN   256
#define HDIM  64
#define WDIM  64
#define HW    4096          // 64*64
#define OUTC  256
#define KKPOS 9             // 3x3
#define CKDIM 2304          // CIN * 9
#define NOFF  27            // 3*K*K offset-conv output channels
#define NPIX  (BATCH * HW)  // 16384

// Fused GEMM config (mma.sync m16n8k8 tf32) — R10 shape, packed fragments
#define TM 256              // CTA M tile (ALL out channels -> gather single-pass)
#define TN 128              // CTA N tile (pixels)
#define TK 32               // K per pipeline chunk
#define NSTAGE 3
#define KCHUNKS (CKDIM / TK)                  // 72
#define A_FLOATS (TM * TK)                    // 8192 (32 KB)
#define B_FLOATS (TN * TK)                    // 4096 (16 KB)
#define STAGE_FLOATS (A_FLOATS + B_FLOATS)    // 12288 (48 KB)
#define REC_OFF (NSTAGE * STAGE_FLOATS)       // float offset of record area
#define GEMM_SMEM_BYTES ((REC_OFF + 2 * 4608) * 4)   // 184320

// Offset-conv GEMM config (M=32 pad of 27, static im2col)
#define TM2 32
#define TN2 128
#define A2_FLOATS (TM2 * TK)                  // 1024 (4 KB)
#define B2_FLOATS (TN2 * TK)                  // 4096 (16 KB)
#define STG2_FLOATS (A2_FLOATS + B2_FLOATS)   // 5120 (20 KB)
#define OM_SMEM_BYTES (NSTAGE * STG2_FLOATS * 4)     // 61440

__device__ __forceinline__ uint32_t smem_u32(const void* p) {
    uint32_t a;
    asm("{ .reg .u64 t; cvta.to.shared.u64 t, %1; cvt.u32.u64 %0, t; }" : "=r"(a) : "l"(p));
    return a;
}
__device__ __forceinline__ void cp16(uint32_t dst, const void* src) {
    asm volatile("cp.async.cg.shared.global [%0], [%1], 16;" :: "r"(dst), "l"(src));
}
__device__ __forceinline__ float to_tf32(float f) {
    uint32_t u;
    asm("cvt.rna.tf32.f32 %0, %1;" : "=r"(u) : "f"(f));
    return __uint_as_float(u);
}
__device__ __forceinline__ void mma_tf32s(float* c,
                                          uint32_t a0, uint32_t a1, uint32_t a2, uint32_t a3,
                                          uint32_t b0, uint32_t b1) {
    asm volatile(
        "mma.sync.aligned.m16n8k8.row.col.f32.tf32.tf32.f32 "
        "{%0,%1,%2,%3}, {%4,%5,%6,%7}, {%8,%9}, {%0,%1,%2,%3};"
        : "+f"(c[0]), "+f"(c[1]), "+f"(c[2]), "+f"(c[3])
        : "r"(a0), "r"(a1), "r"(a2), "r"(a3), "r"(b0), "r"(b1));
}

// ---------------------------------------------------------------------------
// Scratch (static __device__ arrays)
// ---------------------------------------------------------------------------
__device__ int4   g_rec_idx[BATCH * KKPOS * HW];     // 2.36 MB
__device__ float4 g_rec_w  [BATCH * KKPOS * HW];     // 2.36 MB
// Pre-shuffled tf32 main weights (fragment-pair packed, see R10)
__device__ float  g_wt2[KCHUNKS * A_FLOATS];         // 2.36 MB
// Pre-shuffled tf32 offset-conv weights, M padded 27->32, same packing
__device__ float  g_woff2[KCHUNKS * A2_FLOATS];      // 288 KB
// Offset-conv GEMM output om[oc][pixel]
__device__ float  g_om[NOFF * NPIX];                 // 1.77 MB

// ---------------------------------------------------------------------------
// Kernel 0a: round + shuffle main GEMM weight into packed layout.
// ---------------------------------------------------------------------------
__global__ __launch_bounds__(256)
void wprep_kernel(const float* __restrict__ weight)
{
    int i = blockIdx.x * 256 + threadIdx.x;
    if (i >= OUTC * CKDIM) return;
    int half = i & 1;
    int t4   = (i >> 1) & 3;
    int m    = (i >> 3) & 255;
    int ksc  = i >> 11;            // c*4 + ks
    int ks   = ksc & 3;
    int c    = ksc >> 2;
    g_wt2[i] = to_tf32(weight[(size_t)m * CKDIM + c * 32 + ks * 8 + half * 4 + t4]);
}

// ---------------------------------------------------------------------------
// Kernel 0b: round + shuffle offset-conv weight (pad 27->32 with zeros).
// ---------------------------------------------------------------------------
__global__ __launch_bounds__(256)
void wprep_off_kernel(const float* __restrict__ w_off)
{
    int i = blockIdx.x * 256 + threadIdx.x;
    if (i >= KCHUNKS * A2_FLOATS) return;
    int half  = i & 1;
    int t4    = (i >> 1) & 3;
    int m     = (i >> 3) & 31;
    int ks    = (i >> 8) & 3;
    int chunk = i >> 10;
    int k = chunk * 32 + ks * 8 + half * 4 + t4;
    g_woff2[i] = (m < NOFF) ? to_tf32(w_off[(size_t)m * CKDIM + k]) : 0.f;
}

// ---------------------------------------------------------------------------
// Kernel 1: offset conv as tf32 MMA GEMM.
// om[oc][p] = sum_ck w_off[oc][ck] * x_im2col(p, ck)   (static 3x3 im2col)
// CTA: M=32 x N=128 pixels x K=2304, 256 threads (8 warps, warp tile 32x16).
// ---------------------------------------------------------------------------
__device__ __forceinline__ void om_fill_A(float* sm, int stage, int chunk, int tid)
{
    uint32_t sa = smem_u32(sm + stage * STG2_FLOATS);
    const float* src = g_woff2 + (size_t)chunk * A2_FLOATS;
    // 256 cp16, one per thread
    cp16(sa + (uint32_t)tid * 16, src + tid * 4);
    asm volatile("cp.async.commit_group;" ::: "memory");
}

__device__ __forceinline__ void om_fill_B(float* sm, int stage, int chunk, int tid,
                                          const float* __restrict__ xb, int hw0)
{
    const int n  = tid & 127;
    const int h  = tid >> 7;          // 0..1 -> ks pair
    const int hw = hw0 + n;
    const int y  = hw >> 6;
    const int xw = hw & 63;

#pragma unroll
    for (int s2 = 0; s2 < 2; s2++) {
        const int ks = h * 2 + s2;
        const int kb = chunk * TK + ks * 8;
        float r[8];
#pragma unroll
        for (int q = 0; q < 8; q++) {
            int ck = kb + q;
            int c  = ck / KKPOS;
            int j  = ck - c * KKPOS;
            int yy = y + j / 3 - 1;
            int xx = xw + j % 3 - 1;
            bool ok = (yy >= 0 && yy < HDIM && xx >= 0 && xx < WDIM);
            float v = ok ? xb[(size_t)c * HW + yy * WDIM + xx] : 0.f;
            r[q] = to_tf32(v);
        }
        float* sb = sm + stage * STG2_FLOATS + A2_FLOATS + (ks * TN2 + n) * 8;
        *(float4*)(sb + 0) = make_float4(r[0], r[4], r[1], r[5]);
        *(float4*)(sb + 4) = make_float4(r[2], r[6], r[3], r[7]);
    }
}

__global__ __launch_bounds__(256)
void om_gemm_kernel(const float* __restrict__ x)
{
    extern __shared__ float sm[];
    const int tid = threadIdx.x;
    const int wid = tid >> 5;      // 0..7 = wn
    const int lid = tid & 31;
    const int g   = lid >> 2;
    const int t4  = lid & 3;
    const int n0  = blockIdx.x * TN2;
    const int b   = n0 >> 12;
    const int hw0 = n0 & 4095;
    const float* xb = x + (size_t)b * CIN * HW;

    float acc[2][2][4];
#pragma unroll
    for (int i = 0; i < 2; i++)
#pragma unroll
        for (int j = 0; j < 2; j++)
#pragma unroll
            for (int q = 0; q < 4; q++) acc[i][j][q] = 0.f;

    for (int pf = 0; pf < 2; pf++) {
        om_fill_A(sm, pf, pf, tid);
        om_fill_B(sm, pf, pf, tid, xb, hw0);
    }

    for (int i = 0; i < KCHUNKS; i++) {
        const int s = i % NSTAGE;
        if (i == KCHUNKS - 1)
            asm volatile("cp.async.wait_group 0;" ::: "memory");
        else
            asm volatile("cp.async.wait_group 1;" ::: "memory");
        __syncthreads();

        if (i + 2 < KCHUNKS)
            om_fill_A(sm, (i + 2) % NSTAGE, i + 2, tid);

        const uint2* Au2 = (const uint2*)(sm + s * STG2_FLOATS);
        const uint2* Bu2 = (const uint2*)(sm + s * STG2_FLOATS + A2_FLOATS);

#pragma unroll
        for (int ks = 0; ks < 4; ks++) {
            uint2 alo[2], ahi[2], bb[2];
#pragma unroll
            for (int ii = 0; ii < 2; ii++) {
                int m = ii * 16 + g;
                alo[ii] = Au2[(ks * TM2 + m) * 4 + t4];
                ahi[ii] = Au2[(ks * TM2 + m + 8) * 4 + t4];
            }
#pragma unroll
            for (int jj = 0; jj < 2; jj++) {
                int n = wid * 16 + jj * 8 + g;
                bb[jj] = Bu2[(ks * TN2 + n) * 4 + t4];
            }
#pragma unroll
            for (int ii = 0; ii < 2; ii++)
#pragma unroll
                for (int jj = 0; jj < 2; jj++)
                    mma_tf32s(acc[ii][jj],
                              alo[ii].x, ahi[ii].x, alo[ii].y, ahi[ii].y,
                              bb[jj].x, bb[jj].y);
        }

        if (i + 2 < KCHUNKS)
            om_fill_B(sm, (i + 2) % NSTAGE, i + 2, tid, xb, hw0);
    }

    // Epilogue: write om[oc][pixel] for oc < 27.
#pragma unroll
    for (int ii = 0; ii < 2; ii++) {
        int ra = ii * 16 + g;
        int rb = ra + 8;
#pragma unroll
        for (int jj = 0; jj < 2; jj++) {
            int col = n0 + wid * 16 + jj * 8 + 2 * t4;
            if (ra < NOFF)
                *(float2*)&g_om[(size_t)ra * NPIX + col] =
                    make_float2(acc[ii][jj][0], acc[ii][jj][1]);
            if (rb < NOFF)
                *(float2*)&g_om[(size_t)rb * NPIX + col] =
                    make_float2(acc[ii][jj][2], acc[ii][jj][3]);
        }
    }
}

// ---------------------------------------------------------------------------
// Kernel 2: build sampling records from om.
// ---------------------------------------------------------------------------
__global__ __launch_bounds__(256)
void offset_rec_kernel(const float* __restrict__ b_off)
{
    const int gid = blockIdx.x * blockDim.x + threadIdx.x;
    const int b  = gid >> 12;
    const int hw = gid & 4095;
    const int y  = hw >> 6;
    const int xw = hw & 63;

    float acc[NOFF];
#pragma unroll
    for (int oc = 0; oc < NOFF; oc++)
        acc[oc] = b_off[oc] + g_om[(size_t)oc * NPIX + gid];

#pragma unroll
    for (int kp = 0; kp < KKPOS; kp++) {
        float dy = acc[2 * kp];
        float dx = acc[2 * kp + 1];
        float mask = 1.f / (1.f + __expf(-acc[18 + kp]));

        float py = (float)(y  - 1 + kp / 3) + dy;
        float px = (float)(xw - 1 + kp % 3) + dx;
        float y0f = floorf(py), x0f = floorf(px);
        float ly = py - y0f,   lx = px - x0f;
        int y0 = (int)y0f, x0 = (int)x0f;

        int4 idx; float4 wv;
        {
            int yy = y0, xx = x0;
            bool ok = (yy >= 0 && yy < HDIM && xx >= 0 && xx < WDIM);
            int yc = min(max(yy, 0), HDIM - 1), xc = min(max(xx, 0), WDIM - 1);
            idx.x = yc * WDIM + xc;
            wv.x = ok ? (1.f - ly) * (1.f - lx) * mask : 0.f;
        }
        {
            int yy = y0, xx = x0 + 1;
            bool ok = (yy >= 0 && yy < HDIM && xx >= 0 && xx < WDIM);
            int yc = min(max(yy, 0), HDIM - 1), xc = min(max(xx, 0), WDIM - 1);
            idx.y = yc * WDIM + xc;
            wv.y = ok ? (1.f - ly) * lx * mask : 0.f;
        }
        {
            int yy = y0 + 1, xx = x0;
            bool ok = (yy >= 0 && yy < HDIM && xx >= 0 && xx < WDIM);
            int yc = min(max(yy, 0), HDIM - 1), xc = min(max(xx, 0), WDIM - 1);
            idx.z = yc * WDIM + xc;
            wv.z = ok ? ly * (1.f - lx) * mask : 0.f;
        }
        {
            int yy = y0 + 1, xx = x0 + 1;
            bool ok = (yy >= 0 && yy < HDIM && xx >= 0 && xx < WDIM);
            int yc = min(max(yy, 0), HDIM - 1), xc = min(max(xx, 0), WDIM - 1);
            idx.w = yc * WDIM + xc;
            wv.w = ok ? ly * lx * mask : 0.f;
        }

        int r = ((b * KKPOS + kp) << 12) + hw;
        g_rec_idx[r] = idx;
        g_rec_w[r]   = wv;
    }
}

// ---------------------------------------------------------------------------
// Kernel 3 (fused): gather + tf32 mma.sync GEMM — unchanged from R10.
// ---------------------------------------------------------------------------
__device__ __forceinline__ void fill_A(float* sm, int stage, int chunk, int tid)
{
    uint32_t sa = smem_u32(sm + stage * STAGE_FLOATS);
    const float* src = g_wt2 + (size_t)chunk * A_FLOATS;
#pragma unroll
    for (int it = 0; it < 4; it++) {
        int c = tid + it * 512;
        cp16(sa + (uint32_t)c * 16, src + c * 4);
    }
    asm volatile("cp.async.commit_group;" ::: "memory");
}

__device__ __forceinline__ void fill_B(float* sm, int stage, int chunk, int tid,
                                       const float* __restrict__ xb,
                                       const int4* s_idx, const float4* s_w)
{
    const int n  = tid & 127;
    const int ks = tid >> 7;          // 0..3
    const int kb = chunk * TK + ks * 8;
    float r[8];

#pragma unroll
    for (int h = 0; h < 2; h++) {
        float v[16];
#pragma unroll
        for (int j = 0; j < 4; j++) {
            int ck = kb + h * 4 + j;
            int c  = ck / KKPOS;
            int kp = ck - c * KKPOS;
            int4 id = s_idx[kp * TN + n];
            const float* xp = xb + (size_t)c * HW;
            v[j * 4 + 0] = xp[id.x];
            v[j * 4 + 1] = xp[id.y];
            v[j * 4 + 2] = xp[id.z];
            v[j * 4 + 3] = xp[id.w];
        }
#pragma unroll
        for (int j = 0; j < 4; j++) {
            int ck = kb + h * 4 + j;
            int c  = ck / KKPOS;
            int kp = ck - c * KKPOS;
            float4 w = s_w[kp * TN + n];
            r[h * 4 + j] = to_tf32(w.x * v[j * 4 + 0] + w.y * v[j * 4 + 1]
                                 + w.z * v[j * 4 + 2] + w.w * v[j * 4 + 3]);
        }
    }

    float* sb = sm + stage * STAGE_FLOATS + A_FLOATS + (ks * TN + n) * 8;
    *(float4*)(sb + 0) = make_float4(r[0], r[4], r[1], r[5]);
    *(float4*)(sb + 4) = make_float4(r[2], r[6], r[3], r[7]);
}

__global__ __launch_bounds__(512, 1)
void gemm_fused_kernel(const float* __restrict__ x,
                       const float* __restrict__ bias,
                       float* __restrict__ out)
{
    extern __shared__ float sm[];
    const int tid = threadIdx.x;
    const int wid = tid >> 5;
    const int lid = tid & 31;
    const int g   = lid >> 2;
    const int t4  = lid & 3;
    const int wm  = wid & 3;
    const int wn  = wid >> 2;
    const int n0  = blockIdx.x * TN;
    const int b   = n0 >> 12;
    const int hw0 = n0 & 4095;
    const float* xb = x + (size_t)b * CIN * HW;

    int4*   s_idx = (int4*)  (sm + REC_OFF);
    float4* s_w   = (float4*)(sm + REC_OFF + 4608);

    for (int i = tid; i < KKPOS * TN; i += 512) {
        int kp = i >> 7, n = i & 127;
        int r  = ((b * KKPOS + kp) << 12) + hw0 + n;
        s_idx[i] = g_rec_idx[r];
        s_w[i]   = g_rec_w[r];
    }
    __syncthreads();

    float acc[4][4][4];
#pragma unroll
    for (int i = 0; i < 4; i++)
#pragma unroll
        for (int j = 0; j < 4; j++)
#pragma unroll
            for (int q = 0; q < 4; q++) acc[i][j][q] = 0.f;

    for (int pf = 0; pf < 2; pf++) {
        fill_A(sm, pf, pf, tid);
        fill_B(sm, pf, pf, tid, xb, s_idx, s_w);
    }

    for (int i = 0; i < KCHUNKS; i++) {
        const int s = i % NSTAGE;
        if (i == KCHUNKS - 1)
            asm volatile("cp.async.wait_group 0;" ::: "memory");
        else
            asm volatile("cp.async.wait_group 1;" ::: "memory");
        __syncthreads();

        if (i + 2 < KCHUNKS)
            fill_A(sm, (i + 2) % NSTAGE, i + 2, tid);

        const uint2* Au2 = (const uint2*)(sm + s * STAGE_FLOATS);
        const uint2* Bu2 = (const uint2*)(sm + s * STAGE_FLOATS + A_FLOATS);

#pragma unroll
        for (int ks = 0; ks < 4; ks++) {
            uint2 alo[4], ahi[4], bb[4];
#pragma unroll
            for (int ii = 0; ii < 4; ii++) {
                int m = wm * 64 + ii * 16 + g;
                alo[ii] = Au2[(ks * TM + m) * 4 + t4];
                ahi[ii] = Au2[(ks * TM + m + 8) * 4 + t4];
            }
#pragma unroll
            for (int jj = 0; jj < 4; jj++) {
                int n = wn * 32 + jj * 8 + g;
                bb[jj] = Bu2[(ks * TN + n) * 4 + t4];
            }
#pragma unroll
            for (int ii = 0; ii < 4; ii++)
#pragma unroll
                for (int jj = 0; jj < 4; jj++)
                    mma_tf32s(acc[ii][jj],
                              alo[ii].x, ahi[ii].x, alo[ii].y, ahi[ii].y,
                              bb[jj].x, bb[jj].y);
        }

        if (i + 2 < KCHUNKS)
            fill_B(sm, (i + 2) % NSTAGE, i + 2, tid, xb, s_idx, s_w);
    }

#pragma unroll
    for (int ii = 0; ii < 4; ii++) {
        int r0 = wm * 64 + ii * 16 + g;
        float bi0 = bias[r0], bi1 = bias[r0 + 8];
        float* p0 = out + ((size_t)(b * OUTC + r0)) * HW + hw0;
        float* p1 = p0 + (size_t)8 * HW;
#pragma unroll
        for (int jj = 0; jj < 4; jj++) {
            int col = wn * 32 + jj * 8 + 2 * t4;
            float2 v0 = make_float2(acc[ii][jj][0] + bi0, acc[ii][jj][1] + bi0);
            float2 v1 = make_float2(acc[ii][jj][2] + bi1, acc[ii][jj][3] + bi1);
            *(float2*)(p0 + col) = v0;
            *(float2*)(p1 + col) = v1;
        }
    }
}

// ---------------------------------------------------------------------------
// Launch: inputs per metadata order: x, w_off, b_off, weight, bias
// ---------------------------------------------------------------------------
extern "C" void kernel_launch(void* const* d_in, const int* in_sizes, int n_in,
                              void* d_out, int out_size)
{
    const float* x      = (const float*)d_in[0];
    const float* w_off  = (const float*)d_in[1];
    const float* b_off  = (const float*)d_in[2];
    const float* weight = (const float*)d_in[3];
    const float* bias   = (const float*)d_in[4];
    float* out = (float*)d_out;

    cudaFuncSetAttribute(gemm_fused_kernel,
                         cudaFuncAttributeMaxDynamicSharedMemorySize,
                         GEMM_SMEM_BYTES);
    cudaFuncSetAttribute(om_gemm_kernel,
                         cudaFuncAttributeMaxDynamicSharedMemorySize,
                         OM_SMEM_BYTES);

    wprep_kernel<<<(OUTC * CKDIM + 255) / 256, 256>>>(weight);
    wprep_off_kernel<<<(KCHUNKS * A2_FLOATS + 255) / 256, 256>>>(w_off);

    om_gemm_kernel<<<NPIX / TN2, 256, OM_SMEM_BYTES>>>(x);

    offset_rec_kernel<<<NPIX / 256, 256>>>(b_off);

    gemm_fused_kernel<<<NPIX / TN, 512, GEMM_SMEM_BYTES>>>(x, bias, out);
}

// round 12
// speedup vs baseline: 1.9842x; 1.2652x over previous
#include <cuda_runtime.h>
#include <cuda_fp16.h>
#include <cstdint>

// Problem constants
#define BATCH 4
#define CIN   256
#define HDIM  64
#define WDIM  64
#define HW    4096          // 64*64
#define OUTC  256
#define KKPOS 9             // 3x3
#define CKDIM 2304          // CIN * 9
#define NOFF  27            // 3*K*K offset-conv output channels
#define NPIX  (BATCH * HW)  // 16384

// Fused GEMM config (mma.sync m16n8k16 fp16, fp32 accum)
#define TM 256              // CTA M tile (ALL out channels -> gather single-pass)
#define TN 128              // CTA N tile (pixels)
#define TK 32               // K per pipeline chunk (2 x k16)
#define NSTAGE 3
#define KCHUNKS (CKDIM / TK)                  // 72
#define A_BYTES (2 * TM * 4 * 8)              // 16384 (uint2 per [ks16][m][t4])
#define B_BYTES (2 * TN * 4 * 8)              // 8192
#define STAGE_BYTES (A_BYTES + B_BYTES)       // 24576
#define REC_BYTE_OFF (NSTAGE * STAGE_BYTES)   // 73728
#define GEMM_SMEM_BYTES (REC_BYTE_OFF + 2 * 18432)   // 110592

// Offset-conv GEMM config (tf32, M=32 pad of 27, static im2col)
#define TM2 32
#define TN2 128
#define A2_FLOATS (TM2 * TK)                  // 1024 (4 KB)
#define B2_FLOATS (TN2 * TK)                  // 4096 (16 KB)
#define STG2_FLOATS (A2_FLOATS + B2_FLOATS)   // 5120 (20 KB)
#define OM_SMEM_BYTES (NSTAGE * STG2_FLOATS * 4)     // 61440

__device__ __forceinline__ uint32_t smem_u32(const void* p) {
    uint32_t a;
    asm("{ .reg .u64 t; cvta.to.shared.u64 t, %1; cvt.u32.u64 %0, t; }" : "=r"(a) : "l"(p));
    return a;
}
__device__ __forceinline__ void cp16(uint32_t dst, const void* src) {
    asm volatile("cp.async.cg.shared.global [%0], [%1], 16;" :: "r"(dst), "l"(src));
}
__device__ __forceinline__ float to_tf32(float f) {
    uint32_t u;
    asm("cvt.rna.tf32.f32 %0, %1;" : "=r"(u) : "f"(f));
    return __uint_as_float(u);
}
__device__ __forceinline__ uint32_t pack_h2(float a, float b) {
    __half2 h = __floats2half2_rn(a, b);
    return *(uint32_t*)&h;
}
// fp16 MMA, fp32 accumulate
__device__ __forceinline__ void mma_f16(float* c,
                                        uint32_t a0, uint32_t a1, uint32_t a2, uint32_t a3,
                                        uint32_t b0, uint32_t b1) {
    asm volatile(
        "mma.sync.aligned.m16n8k16.row.col.f32.f16.f16.f32 "
        "{%0,%1,%2,%3}, {%4,%5,%6,%7}, {%8,%9}, {%0,%1,%2,%3};"
        : "+f"(c[0]), "+f"(c[1]), "+f"(c[2]), "+f"(c[3])
        : "r"(a0), "r"(a1), "r"(a2), "r"(a3), "r"(b0), "r"(b1));
}
// tf32 MMA (om path)
__device__ __forceinline__ void mma_tf32s(float* c,
                                          uint32_t a0, uint32_t a1, uint32_t a2, uint32_t a3,
                                          uint32_t b0, uint32_t b1) {
    asm volatile(
        "mma.sync.aligned.m16n8k8.row.col.f32.tf32.tf32.f32 "
        "{%0,%1,%2,%3}, {%4,%5,%6,%7}, {%8,%9}, {%0,%1,%2,%3};"
        : "+f"(c[0]), "+f"(c[1]), "+f"(c[2]), "+f"(c[3])
        : "r"(a0), "r"(a1), "r"(a2), "r"(a3), "r"(b0), "r"(b1));
}

// ---------------------------------------------------------------------------
// Scratch (static __device__ arrays)
// ---------------------------------------------------------------------------
__device__ int4   g_rec_idx[BATCH * KKPOS * HW];     // 2.36 MB
__device__ float4 g_rec_w  [BATCH * KKPOS * HW];     // 2.36 MB
// fp16 fragment-packed main weights: [chunk][ks16][m][t4] uint2
// .x = half2(W[m][kb+2t4], W[m][kb+2t4+1]); .y = half2(W[m][kb+8+2t4], +9)
__device__ uint2  g_wt2h[KCHUNKS * 2 * TM * 4];      // 1.18 MB
// tf32 offset-conv weights, M padded 27->32 (R11 packing)
__device__ float  g_woff2[KCHUNKS * A2_FLOATS];      // 288 KB
__device__ float  g_om[NOFF * NPIX];                 // 1.77 MB

// ---------------------------------------------------------------------------
// Kernel 0a: pack main weight to fp16 fragment layout.
// ---------------------------------------------------------------------------
__global__ __launch_bounds__(256)
void wprep_kernel(const float* __restrict__ weight)
{
    int i = blockIdx.x * 256 + threadIdx.x;
    if (i >= KCHUNKS * 2 * TM * 4) return;
    int t4    = i & 3;
    int m     = (i >> 2) & 255;
    int ks16  = (i >> 10) & 1;
    int chunk = i >> 11;
    int kb = chunk * 32 + ks16 * 16;
    const float* wr = weight + (size_t)m * CKDIM;
    uint2 v;
    v.x = pack_h2(wr[kb + 2 * t4],     wr[kb + 2 * t4 + 1]);
    v.y = pack_h2(wr[kb + 8 + 2 * t4], wr[kb + 8 + 2 * t4 + 1]);
    g_wt2h[i] = v;
}

// ---------------------------------------------------------------------------
// Kernel 0b: round + shuffle offset-conv weight (pad 27->32 with zeros).
// ---------------------------------------------------------------------------
__global__ __launch_bounds__(256)
void wprep_off_kernel(const float* __restrict__ w_off)
{
    int i = blockIdx.x * 256 + threadIdx.x;
    if (i >= KCHUNKS * A2_FLOATS) return;
    int half  = i & 1;
    int t4    = (i >> 1) & 3;
    int m     = (i >> 3) & 31;
    int ks    = (i >> 8) & 3;
    int chunk = i >> 10;
    int k = chunk * 32 + ks * 8 + half * 4 + t4;
    g_woff2[i] = (m < NOFF) ? to_tf32(w_off[(size_t)m * CKDIM + k]) : 0.f;
}

// ---------------------------------------------------------------------------
// Kernel 1: offset conv as tf32 MMA GEMM — now 512 threads (16 warps).
// Warp tile 16(M) x 16(N): wm = wid&1, wn = wid>>1.
// ---------------------------------------------------------------------------
__device__ __forceinline__ void om_fill_A(float* sm, int stage, int chunk, int tid)
{
    if (tid < 256) {
        uint32_t sa = smem_u32(sm + stage * STG2_FLOATS);
        const float* src = g_woff2 + (size_t)chunk * A2_FLOATS;
        cp16(sa + (uint32_t)tid * 16, src + tid * 4);
    }
    asm volatile("cp.async.commit_group;" ::: "memory");
}

__device__ __forceinline__ void om_fill_B(float* sm, int stage, int chunk, int tid,
                                          const float* __restrict__ xb, int hw0)
{
    const int n   = tid & 127;
    const int ksq = tid >> 7;         // 0..3
    const int hw  = hw0 + n;
    const int y   = hw >> 6;
    const int xw  = hw & 63;
    const int kb  = chunk * TK + ksq * 8;

    float r[8];
#pragma unroll
    for (int q = 0; q < 8; q++) {
        int ck = kb + q;
        int c  = ck / KKPOS;
        int j  = ck - c * KKPOS;
        int yy = y + j / 3 - 1;
        int xx = xw + j % 3 - 1;
        bool ok = (yy >= 0 && yy < HDIM && xx >= 0 && xx < WDIM);
        float v = ok ? xb[(size_t)c * HW + yy * WDIM + xx] : 0.f;
        r[q] = to_tf32(v);
    }
    float* sb = sm + stage * STG2_FLOATS + A2_FLOATS + (ksq * TN2 + n) * 8;
    *(float4*)(sb + 0) = make_float4(r[0], r[4], r[1], r[5]);
    *(float4*)(sb + 4) = make_float4(r[2], r[6], r[3], r[7]);
}

__global__ __launch_bounds__(512)
void om_gemm_kernel(const float* __restrict__ x)
{
    extern __shared__ float sm[];
    const int tid = threadIdx.x;
    const int wid = tid >> 5;
    const int lid = tid & 31;
    const int g   = lid >> 2;
    const int t4  = lid & 3;
    const int wm  = wid & 1;       // M half (16 rows)
    const int wn  = wid >> 1;      // N (16 cols)
    const int n0  = blockIdx.x * TN2;
    const int b   = n0 >> 12;
    const int hw0 = n0 & 4095;
    const float* xb = x + (size_t)b * CIN * HW;

    float acc[2][4];
#pragma unroll
    for (int j = 0; j < 2; j++)
#pragma unroll
        for (int q = 0; q < 4; q++) acc[j][q] = 0.f;

    for (int pf = 0; pf < 2; pf++) {
        om_fill_A(sm, pf, pf, tid);
        om_fill_B(sm, pf, pf, tid, xb, hw0);
    }

    for (int i = 0; i < KCHUNKS; i++) {
        const int s = i % NSTAGE;
        if (i == KCHUNKS - 1)
            asm volatile("cp.async.wait_group 0;" ::: "memory");
        else
            asm volatile("cp.async.wait_group 1;" ::: "memory");
        __syncthreads();

        if (i + 2 < KCHUNKS)
            om_fill_A(sm, (i + 2) % NSTAGE, i + 2, tid);

        const uint2* Au2 = (const uint2*)(sm + s * STG2_FLOATS);
        const uint2* Bu2 = (const uint2*)(sm + s * STG2_FLOATS + A2_FLOATS);

#pragma unroll
        for (int ks = 0; ks < 4; ks++) {
            int m = wm * 16 + g;
            uint2 alo = Au2[(ks * TM2 + m) * 4 + t4];
            uint2 ahi = Au2[(ks * TM2 + m + 8) * 4 + t4];
            uint2 bb[2];
#pragma unroll
            for (int jj = 0; jj < 2; jj++) {
                int n = wn * 16 + jj * 8 + g;
                bb[jj] = Bu2[(ks * TN2 + n) * 4 + t4];
            }
#pragma unroll
            for (int jj = 0; jj < 2; jj++)
                mma_tf32s(acc[jj], alo.x, ahi.x, alo.y, ahi.y,
                          bb[jj].x, bb[jj].y);
        }

        if (i + 2 < KCHUNKS)
            om_fill_B(sm, (i + 2) % NSTAGE, i + 2, tid, xb, hw0);
    }

    // Epilogue: write om[oc][pixel] for oc < 27.
    int ra = wm * 16 + g;
    int rb = ra + 8;
#pragma unroll
    for (int jj = 0; jj < 2; jj++) {
        int col = n0 + wn * 16 + jj * 8 + 2 * t4;
        if (ra < NOFF)
            *(float2*)&g_om[(size_t)ra * NPIX + col] =
                make_float2(acc[jj][0], acc[jj][1]);
        if (rb < NOFF)
            *(float2*)&g_om[(size_t)rb * NPIX + col] =
                make_float2(acc[jj][2], acc[jj][3]);
    }
}

// ---------------------------------------------------------------------------
// Kernel 2: build sampling records from om. (unchanged)
// ---------------------------------------------------------------------------
__global__ __launch_bounds__(256)
void offset_rec_kernel(const float* __restrict__ b_off)
{
    const int gid = blockIdx.x * blockDim.x + threadIdx.x;
    const int b  = gid >> 12;
    const int hw = gid & 4095;
    const int y  = hw >> 6;
    const int xw = hw & 63;

    float acc[NOFF];
#pragma unroll
    for (int oc = 0; oc < NOFF; oc++)
        acc[oc] = b_off[oc] + g_om[(size_t)oc * NPIX + gid];

#pragma unroll
    for (int kp = 0; kp < KKPOS; kp++) {
        float dy = acc[2 * kp];
        float dx = acc[2 * kp + 1];
        float mask = 1.f / (1.f + __expf(-acc[18 + kp]));

        float py = (float)(y  - 1 + kp / 3) + dy;
        float px = (float)(xw - 1 + kp % 3) + dx;
        float y0f = floorf(py), x0f = floorf(px);
        float ly = py - y0f,   lx = px - x0f;
        int y0 = (int)y0f, x0 = (int)x0f;

        int4 idx; float4 wv;
        {
            int yy = y0, xx = x0;
            bool ok = (yy >= 0 && yy < HDIM && xx >= 0 && xx < WDIM);
            int yc = min(max(yy, 0), HDIM - 1), xc = min(max(xx, 0), WDIM - 1);
            idx.x = yc * WDIM + xc;
            wv.x = ok ? (1.f - ly) * (1.f - lx) * mask : 0.f;
        }
        {
            int yy = y0, xx = x0 + 1;
            bool ok = (yy >= 0 && yy < HDIM && xx >= 0 && xx < WDIM);
            int yc = min(max(yy, 0), HDIM - 1), xc = min(max(xx, 0), WDIM - 1);
            idx.y = yc * WDIM + xc;
            wv.y = ok ? (1.f - ly) * lx * mask : 0.f;
        }
        {
            int yy = y0 + 1, xx = x0;
            bool ok = (yy >= 0 && yy < HDIM && xx >= 0 && xx < WDIM);
            int yc = min(max(yy, 0), HDIM - 1), xc = min(max(xx, 0), WDIM - 1);
            idx.z = yc * WDIM + xc;
            wv.z = ok ? ly * (1.f - lx) * mask : 0.f;
        }
        {
            int yy = y0 + 1, xx = x0 + 1;
            bool ok = (yy >= 0 && yy < HDIM && xx >= 0 && xx < WDIM);
            int yc = min(max(yy, 0), HDIM - 1), xc = min(max(xx, 0), WDIM - 1);
            idx.w = yc * WDIM + xc;
            wv.w = ok ? ly * lx * mask : 0.f;
        }

        int r = ((b * KKPOS + kp) << 12) + hw;
        g_rec_idx[r] = idx;
        g_rec_w[r]   = wv;
    }
}

// ---------------------------------------------------------------------------
// Kernel 3 (fused): gather + fp16 mma.sync GEMM.
// SMEM per stage: A uint2[2][256][4] (16 KB), B uint2[2][128][4] (8 KB),
// B slot-swizzled: slot = (t4 + (n>>2)) & 3 (conflict-free STS.64 + LDS.64).
// Per warp per chunk: 24 lds.64 + 32 mma (vs 48 + 64 in tf32).
// ---------------------------------------------------------------------------
__device__ __forceinline__ void fill_A(char* sm, int stage, int chunk, int tid)
{
    uint32_t sa = smem_u32(sm + stage * STAGE_BYTES);
    const char* src = (const char*)(g_wt2h + (size_t)chunk * (2 * TM * 4));
#pragma unroll
    for (int it = 0; it < 2; it++) {
        int c = tid + it * 512;
        cp16(sa + (uint32_t)c * 16, src + c * 16);
    }
    asm volatile("cp.async.commit_group;" ::: "memory");
}

// Thread (n = tid&127, t4q = tid>>7) fills both ks16 cells' t4q slot:
// k-values {2t4q, 2t4q+1, 2t4q+8, 2t4q+9} per ks16 (32 gathers total).
__device__ __forceinline__ void fill_B(char* sm, int stage, int chunk, int tid,
                                       const float* __restrict__ xb,
                                       const int4* s_idx, const float4* s_w)
{
    const int n   = tid & 127;
    const int t4q = tid >> 7;         // 0..3
    const int slot = (t4q + (n >> 2)) & 3;
    uint2* sb = (uint2*)(sm + stage * STAGE_BYTES + A_BYTES);

#pragma unroll
    for (int ks16 = 0; ks16 < 2; ks16++) {
        const int kb = chunk * TK + ks16 * 16;
        const int kk0 = 2 * t4q;
        float r[4];
        float v[16];
        const int kidx[4] = { kk0, kk0 + 1, kk0 + 8, kk0 + 9 };
#pragma unroll
        for (int j = 0; j < 4; j++) {
            int ck = kb + kidx[j];
            int c  = ck / KKPOS;
            int kp = ck - c * KKPOS;
            int4 id = s_idx[kp * TN + n];
            const float* xp = xb + (size_t)c * HW;
            v[j * 4 + 0] = xp[id.x];
            v[j * 4 + 1] = xp[id.y];
            v[j * 4 + 2] = xp[id.z];
            v[j * 4 + 3] = xp[id.w];
        }
#pragma unroll
        for (int j = 0; j < 4; j++) {
            int ck = kb + kidx[j];
            int c  = ck / KKPOS;
            int kp = ck - c * KKPOS;
            float4 w = s_w[kp * TN + n];
            r[j] = w.x * v[j * 4 + 0] + w.y * v[j * 4 + 1]
                 + w.z * v[j * 4 + 2] + w.w * v[j * 4 + 3];
        }
        uint2 cell;
        cell.x = pack_h2(r[0], r[1]);   // b0: k = 2t4, 2t4+1
        cell.y = pack_h2(r[2], r[3]);   // b1: k = 2t4+8, 2t4+9
        sb[(ks16 * TN + n) * 4 + slot] = cell;
    }
}

__global__ __launch_bounds__(512, 1)
void gemm_fused_kernel(const float* __restrict__ x,
                       const float* __restrict__ bias,
                       float* __restrict__ out)
{
    extern __shared__ char smc[];
    char* sm = smc;
    const int tid = threadIdx.x;
    const int wid = tid >> 5;
    const int lid = tid & 31;
    const int g   = lid >> 2;
    const int t4  = lid & 3;
    const int wm  = wid & 3;       // M quarter (64 rows)
    const int wn  = wid >> 2;      // N quarter (32 cols)
    const int n0  = blockIdx.x * TN;
    const int b   = n0 >> 12;
    const int hw0 = n0 & 4095;
    const float* xb = x + (size_t)b * CIN * HW;

    int4*   s_idx = (int4*)  (sm + REC_BYTE_OFF);
    float4* s_w   = (float4*)(sm + REC_BYTE_OFF + 18432);

    for (int i = tid; i < KKPOS * TN; i += 512) {
        int kp = i >> 7, n = i & 127;
        int r  = ((b * KKPOS + kp) << 12) + hw0 + n;
        s_idx[i] = g_rec_idx[r];
        s_w[i]   = g_rec_w[r];
    }
    __syncthreads();

    float acc[4][4][4];
#pragma unroll
    for (int i = 0; i < 4; i++)
#pragma unroll
        for (int j = 0; j < 4; j++)
#pragma unroll
            for (int q = 0; q < 4; q++) acc[i][j][q] = 0.f;

    for (int pf = 0; pf < 2; pf++) {
        fill_A(sm, pf, pf, tid);
        fill_B(sm, pf, pf, tid, xb, s_idx, s_w);
    }

    for (int i = 0; i < KCHUNKS; i++) {
        const int s = i % NSTAGE;
        if (i == KCHUNKS - 1)
            asm volatile("cp.async.wait_group 0;" ::: "memory");
        else
            asm volatile("cp.async.wait_group 1;" ::: "memory");
        __syncthreads();   // publishes B(i), frees stage (i+2)%NSTAGE

        if (i + 2 < KCHUNKS)
            fill_A(sm, (i + 2) % NSTAGE, i + 2, tid);

        const uint2* Au2 = (const uint2*)(sm + s * STAGE_BYTES);
        const uint2* Bu2 = (const uint2*)(sm + s * STAGE_BYTES + A_BYTES);

#pragma unroll
        for (int ks16 = 0; ks16 < 2; ks16++) {
            uint2 alo[4], ahi[4], bb[4];
#pragma unroll
            for (int ii = 0; ii < 4; ii++) {
                int m = wm * 64 + ii * 16 + g;
                alo[ii] = Au2[(ks16 * TM + m) * 4 + t4];
                ahi[ii] = Au2[(ks16 * TM + m + 8) * 4 + t4];
            }
#pragma unroll
            for (int jj = 0; jj < 4; jj++) {
                int n = wn * 32 + jj * 8 + g;
                bb[jj] = Bu2[(ks16 * TN + n) * 4 + ((t4 + (n >> 2)) & 3)];
            }
#pragma unroll
            for (int ii = 0; ii < 4; ii++)
#pragma unroll
                for (int jj = 0; jj < 4; jj++)
                    mma_f16(acc[ii][jj],
                            alo[ii].x, ahi[ii].x, alo[ii].y, ahi[ii].y,
                            bb[jj].x, bb[jj].y);
        }

        if (i + 2 < KCHUNKS)
            fill_B(sm, (i + 2) % NSTAGE, i + 2, tid, xb, s_idx, s_w);
    }

    // Epilogue: add bias, store (C fragment layout identical to k8 path).
#pragma unroll
    for (int ii = 0; ii < 4; ii++) {
        int r0 = wm * 64 + ii * 16 + g;
        float bi0 = bias[r0], bi1 = bias[r0 + 8];
        float* p0 = out + ((size_t)(b * OUTC + r0)) * HW + hw0;
        float* p1 = p0 + (size_t)8 * HW;
#pragma unroll
        for (int jj = 0; jj < 4; jj++) {
            int col = wn * 32 + jj * 8 + 2 * t4;
            float2 v0 = make_float2(acc[ii][jj][0] + bi0, acc[ii][jj][1] + bi0);
            float2 v1 = make_float2(acc[ii][jj][2] + bi1, acc[ii][jj][3] + bi1);
            *(float2*)(p0 + col) = v0;
            *(float2*)(p1 + col) = v1;
        }
    }
}

// ---------------------------------------------------------------------------
// Launch: inputs per metadata order: x, w_off, b_off, weight, bias
// ---------------------------------------------------------------------------
extern "C" void kernel_launch(void* const* d_in, const int* in_sizes, int n_in,
                              void* d_out, int out_size)
{
    const float* x      = (const float*)d_in[0];
    const float* w_off  = (const float*)d_in[1];
    const float* b_off  = (const float*)d_in[2];
    const float* weight = (const float*)d_in[3];
    const float* bias   = (const float*)d_in[4];
    float* out = (float*)d_out;

    cudaFuncSetAttribute(gemm_fused_kernel,
                         cudaFuncAttributeMaxDynamicSharedMemorySize,
                         GEMM_SMEM_BYTES);
    cudaFuncSetAttribute(om_gemm_kernel,
                         cudaFuncAttributeMaxDynamicSharedMemorySize,
                         OM_SMEM_BYTES);

    wprep_kernel<<<(KCHUNKS * 2 * TM * 4 + 255) / 256, 256>>>(weight);
    wprep_off_kernel<<<(KCHUNKS * A2_FLOATS + 255) / 256, 256>>>(w_off);

    om_gemm_kernel<<<NPIX / TN2, 512, OM_SMEM_BYTES>>>(x);

    offset_rec_kernel<<<NPIX / 256, 256>>>(b_off);

    gemm_fused_kernel<<<NPIX / TN, 512, GEMM_SMEM_BYTES>>>(x, bias, out);
}

// round 13
// speedup vs baseline: 2.1564x; 1.0868x over previous
#include <cuda_runtime.h>
#include <cuda_fp16.h>
#include <cstdint>

// Problem constants
#define BATCH 4
#define CIN   256
#define HDIM  64
#define WDIM  64
#define HW    4096          // 64*64
#define OUTC  256
#define KKPOS 9             // 3x3
#define CKDIM 2304          // CIN * 9
#define NOFF  27            // 3*K*K offset-conv output channels
#define NPIX  (BATCH * HW)  // 16384

// Fused GEMM config (mma.sync m16n8k16 fp16, fp32 accum) — R12 proven
#define TM 256
#define TN 128
#define TK 32
#define NSTAGE 3
#define KCHUNKS (CKDIM / TK)                  // 72
#define A_BYTES (2 * TM * 4 * 8)              // 16384
#define B_BYTES (2 * TN * 4 * 8)              // 8192
#define STAGE_BYTES (A_BYTES + B_BYTES)       // 24576
#define REC_BYTE_OFF (NSTAGE * STAGE_BYTES)   // 73728
#define GEMM_SMEM_BYTES (REC_BYTE_OFF + 2 * 18432)   // 110592

// Offset-conv GEMM config (fp16, M=32 pad of 27, static im2col, fused rec)
#define TM2 32
#define TN2 128
#define A2_BYTES (2 * TM2 * 4 * 8)            // 2048
#define B2_BYTES (2 * TN2 * 4 * 8)            // 8192
#define STG2_BYTES (A2_BYTES + B2_BYTES)      // 10240
#define OM_SMEM_BYTES (NSTAGE * STG2_BYTES)   // 30720 (>= 16 KB som transpose)

__device__ __forceinline__ uint32_t smem_u32(const void* p) {
    uint32_t a;
    asm("{ .reg .u64 t; cvta.to.shared.u64 t, %1; cvt.u32.u64 %0, t; }" : "=r"(a) : "l"(p));
    return a;
}
__device__ __forceinline__ void cp16(uint32_t dst, const void* src) {
    asm volatile("cp.async.cg.shared.global [%0], [%1], 16;" :: "r"(dst), "l"(src));
}
__device__ __forceinline__ uint32_t pack_h2(float a, float b) {
    __half2 h = __floats2half2_rn(a, b);
    return *(uint32_t*)&h;
}
__device__ __forceinline__ void mma_f16(float* c,
                                        uint32_t a0, uint32_t a1, uint32_t a2, uint32_t a3,
                                        uint32_t b0, uint32_t b1) {
    asm volatile(
        "mma.sync.aligned.m16n8k16.row.col.f32.f16.f16.f32 "
        "{%0,%1,%2,%3}, {%4,%5,%6,%7}, {%8,%9}, {%0,%1,%2,%3};"
        : "+f"(c[0]), "+f"(c[1]), "+f"(c[2]), "+f"(c[3])
        : "r"(a0), "r"(a1), "r"(a2), "r"(a3), "r"(b0), "r"(b1));
}

// ---------------------------------------------------------------------------
// Scratch (static __device__ arrays)
// ---------------------------------------------------------------------------
__device__ int4   g_rec_idx[BATCH * KKPOS * HW];     // 2.36 MB
__device__ float4 g_rec_w  [BATCH * KKPOS * HW];     // 2.36 MB
// fp16 fragment-packed main weights: [chunk][ks16][m][t4] uint2
__device__ uint2  g_wt2h[KCHUNKS * 2 * TM * 4];      // 1.18 MB
// fp16 fragment-packed offset-conv weights, M padded 27->32
__device__ uint2  g_woff2h[KCHUNKS * 2 * TM2 * 4];   // 147 KB

// ---------------------------------------------------------------------------
// Kernel 0a: pack main weight to fp16 fragment layout.
// ---------------------------------------------------------------------------
__global__ __launch_bounds__(256)
void wprep_kernel(const float* __restrict__ weight)
{
    int i = blockIdx.x * 256 + threadIdx.x;
    if (i >= KCHUNKS * 2 * TM * 4) return;
    int t4    = i & 3;
    int m     = (i >> 2) & 255;
    int ks16  = (i >> 10) & 1;
    int chunk = i >> 11;
    int kb = chunk * 32 + ks16 * 16;
    const float* wr = weight + (size_t)m * CKDIM;
    uint2 v;
    v.x = pack_h2(wr[kb + 2 * t4],     wr[kb + 2 * t4 + 1]);
    v.y = pack_h2(wr[kb + 8 + 2 * t4], wr[kb + 8 + 2 * t4 + 1]);
    g_wt2h[i] = v;
}

// ---------------------------------------------------------------------------
// Kernel 0b: pack offset-conv weight to fp16 (pad 27->32 with zeros).
// ---------------------------------------------------------------------------
__global__ __launch_bounds__(256)
void wprep_off_kernel(const float* __restrict__ w_off)
{
    int i = blockIdx.x * 256 + threadIdx.x;
    if (i >= KCHUNKS * 2 * TM2 * 4) return;
    int t4    = i & 3;
    int m     = (i >> 2) & 31;
    int ks16  = (i >> 7) & 1;
    int chunk = i >> 8;
    int kb = chunk * 32 + ks16 * 16;
    uint2 v;
    if (m < NOFF) {
        const float* wr = w_off + (size_t)m * CKDIM;
        v.x = pack_h2(wr[kb + 2 * t4],     wr[kb + 2 * t4 + 1]);
        v.y = pack_h2(wr[kb + 8 + 2 * t4], wr[kb + 8 + 2 * t4 + 1]);
    } else {
        v.x = 0u; v.y = 0u;
    }
    g_woff2h[i] = v;
}

// ---------------------------------------------------------------------------
// Kernel 1: offset conv as fp16 MMA GEMM + FUSED record build.
// om[oc][p] = sum_ck w_off[oc][ck] * x_im2col(p, ck), then per pixel:
// dy/dx/mask -> bilinear sampling records, all in one kernel.
// 512 threads (16 warps, warp tile 16(M) x 16(N)), grid 128.
// ---------------------------------------------------------------------------
__device__ __forceinline__ void om_fill_A(char* sm, int stage, int chunk, int tid)
{
    if (tid < 128) {
        uint32_t sa = smem_u32(sm + stage * STG2_BYTES);
        const char* src = (const char*)(g_woff2h + (size_t)chunk * (2 * TM2 * 4));
        cp16(sa + (uint32_t)tid * 16, src + tid * 16);
    }
    asm volatile("cp.async.commit_group;" ::: "memory");
}

__device__ __forceinline__ void om_fill_B(char* sm, int stage, int chunk, int tid,
                                          const float* __restrict__ xb, int hw0)
{
    const int n   = tid & 127;
    const int t4q = tid >> 7;
    const int slot = (t4q + (n >> 2)) & 3;
    const int hw  = hw0 + n;
    const int y   = hw >> 6;
    const int xw  = hw & 63;
    uint2* sb = (uint2*)(sm + stage * STG2_BYTES + A2_BYTES);

#pragma unroll
    for (int ks16 = 0; ks16 < 2; ks16++) {
        const int kb = chunk * TK + ks16 * 16;
        const int kk0 = 2 * t4q;
        const int kidx[4] = { kk0, kk0 + 1, kk0 + 8, kk0 + 9 };
        float r[4];
#pragma unroll
        for (int j = 0; j < 4; j++) {
            int ck = kb + kidx[j];
            int c  = ck / KKPOS;
            int j9 = ck - c * KKPOS;
            int yy = y + j9 / 3 - 1;
            int xx = xw + j9 % 3 - 1;
            bool ok = (yy >= 0 && yy < HDIM && xx >= 0 && xx < WDIM);
            r[j] = ok ? xb[(size_t)c * HW + yy * WDIM + xx] : 0.f;
        }
        uint2 cell;
        cell.x = pack_h2(r[0], r[1]);
        cell.y = pack_h2(r[2], r[3]);
        sb[(ks16 * TN2 + n) * 4 + slot] = cell;
    }
}

__global__ __launch_bounds__(512)
void om_gemm_kernel(const float* __restrict__ x,
                    const float* __restrict__ b_off)
{
    extern __shared__ char smc[];
    char* sm = smc;
    const int tid = threadIdx.x;
    const int wid = tid >> 5;
    const int lid = tid & 31;
    const int g   = lid >> 2;
    const int t4  = lid & 3;
    const int wm  = wid & 1;       // M half (16 rows)
    const int wn  = wid >> 1;      // N sixteenth (16 cols)
    const int n0  = blockIdx.x * TN2;
    const int b   = n0 >> 12;
    const int hw0 = n0 & 4095;
    const float* xb = x + (size_t)b * CIN * HW;

    float acc[2][4];
#pragma unroll
    for (int j = 0; j < 2; j++)
#pragma unroll
        for (int q = 0; q < 4; q++) acc[j][q] = 0.f;

    for (int pf = 0; pf < 2; pf++) {
        om_fill_A(sm, pf, pf, tid);
        om_fill_B(sm, pf, pf, tid, xb, hw0);
    }

    for (int i = 0; i < KCHUNKS; i++) {
        const int s = i % NSTAGE;
        if (i == KCHUNKS - 1)
            asm volatile("cp.async.wait_group 0;" ::: "memory");
        else
            asm volatile("cp.async.wait_group 1;" ::: "memory");
        __syncthreads();

        if (i + 2 < KCHUNKS)
            om_fill_A(sm, (i + 2) % NSTAGE, i + 2, tid);

        const uint2* Au2 = (const uint2*)(sm + s * STG2_BYTES);
        const uint2* Bu2 = (const uint2*)(sm + s * STG2_BYTES + A2_BYTES);

#pragma unroll
        for (int ks16 = 0; ks16 < 2; ks16++) {
            int m = wm * 16 + g;
            uint2 alo = Au2[(ks16 * TM2 + m) * 4 + t4];
            uint2 ahi = Au2[(ks16 * TM2 + m + 8) * 4 + t4];
            uint2 bb[2];
#pragma unroll
            for (int jj = 0; jj < 2; jj++) {
                int n = wn * 16 + jj * 8 + g;
                bb[jj] = Bu2[(ks16 * TN2 + n) * 4 + ((t4 + (n >> 2)) & 3)];
            }
#pragma unroll
            for (int jj = 0; jj < 2; jj++)
                mma_f16(acc[jj], alo.x, ahi.x, alo.y, ahi.y,
                        bb[jj].x, bb[jj].y);
        }

        if (i + 2 < KCHUNKS)
            om_fill_B(sm, (i + 2) % NSTAGE, i + 2, tid, xb, hw0);
    }

    // ---- Fused epilogue: transpose acc to som[32][128], then rec ----
    __syncthreads();                 // all MMA reads of stage smem done
    float* som = (float*)sm;         // 32 x 128 floats = 16 KB (fits in 30 KB)

    {
        int ra = wm * 16 + g;
        int rb = ra + 8;
#pragma unroll
        for (int jj = 0; jj < 2; jj++) {
            int col = wn * 16 + jj * 8 + 2 * t4;
            *(float2*)&som[ra * TN2 + col] = make_float2(acc[jj][0], acc[jj][1]);
            *(float2*)&som[rb * TN2 + col] = make_float2(acc[jj][2], acc[jj][3]);
        }
    }
    __syncthreads();

    if (tid < TN2) {
        const int hw = hw0 + tid;
        const int y  = hw >> 6;
        const int xw = hw & 63;

        float a[NOFF];
#pragma unroll
        for (int oc = 0; oc < NOFF; oc++)
            a[oc] = b_off[oc] + som[oc * TN2 + tid];

#pragma unroll
        for (int kp = 0; kp < KKPOS; kp++) {
            float dy = a[2 * kp];
            float dx = a[2 * kp + 1];
            float mask = 1.f / (1.f + __expf(-a[18 + kp]));

            float py = (float)(y  - 1 + kp / 3) + dy;
            float px = (float)(xw - 1 + kp % 3) + dx;
            float y0f = floorf(py), x0f = floorf(px);
            float ly = py - y0f,   lx = px - x0f;
            int y0 = (int)y0f, x0 = (int)x0f;

            int4 idx; float4 wv;
            {
                int yy = y0, xx = x0;
                bool ok = (yy >= 0 && yy < HDIM && xx >= 0 && xx < WDIM);
                int yc = min(max(yy, 0), HDIM - 1), xc = min(max(xx, 0), WDIM - 1);
                idx.x = yc * WDIM + xc;
                wv.x = ok ? (1.f - ly) * (1.f - lx) * mask : 0.f;
            }
            {
                int yy = y0, xx = x0 + 1;
                bool ok = (yy >= 0 && yy < HDIM && xx >= 0 && xx < WDIM);
                int yc = min(max(yy, 0), HDIM - 1), xc = min(max(xx, 0), WDIM - 1);
                idx.y = yc * WDIM + xc;
                wv.y = ok ? (1.f - ly) * lx * mask : 0.f;
            }
            {
                int yy = y0 + 1, xx = x0;
                bool ok = (yy >= 0 && yy < HDIM && xx >= 0 && xx < WDIM);
                int yc = min(max(yy, 0), HDIM - 1), xc = min(max(xx, 0), WDIM - 1);
                idx.z = yc * WDIM + xc;
                wv.z = ok ? ly * (1.f - lx) * mask : 0.f;
            }
            {
                int yy = y0 + 1, xx = x0 + 1;
                bool ok = (yy >= 0 && yy < HDIM && xx >= 0 && xx < WDIM);
                int yc = min(max(yy, 0), HDIM - 1), xc = min(max(xx, 0), WDIM - 1);
                idx.w = yc * WDIM + xc;
                wv.w = ok ? ly * lx * mask : 0.f;
            }

            int r = ((b * KKPOS + kp) << 12) + hw;
            g_rec_idx[r] = idx;
            g_rec_w[r]   = wv;
        }
    }
}

// ---------------------------------------------------------------------------
// Kernel 2 (fused): gather + fp16 mma.sync GEMM — unchanged from R12.
// ---------------------------------------------------------------------------
__device__ __forceinline__ void fill_A(char* sm, int stage, int chunk, int tid)
{
    uint32_t sa = smem_u32(sm + stage * STAGE_BYTES);
    const char* src = (const char*)(g_wt2h + (size_t)chunk * (2 * TM * 4));
#pragma unroll
    for (int it = 0; it < 2; it++) {
        int c = tid + it * 512;
        cp16(sa + (uint32_t)c * 16, src + c * 16);
    }
    asm volatile("cp.async.commit_group;" ::: "memory");
}

__device__ __forceinline__ void fill_B(char* sm, int stage, int chunk, int tid,
                                       const float* __restrict__ xb,
                                       const int4* s_idx, const float4* s_w)
{
    const int n   = tid & 127;
    const int t4q = tid >> 7;
    const int slot = (t4q + (n >> 2)) & 3;
    uint2* sb = (uint2*)(sm + stage * STAGE_BYTES + A_BYTES);

#pragma unroll
    for (int ks16 = 0; ks16 < 2; ks16++) {
        const int kb = chunk * TK + ks16 * 16;
        const int kk0 = 2 * t4q;
        float r[4];
        float v[16];
        const int kidx[4] = { kk0, kk0 + 1, kk0 + 8, kk0 + 9 };
#pragma unroll
        for (int j = 0; j < 4; j++) {
            int ck = kb + kidx[j];
            int c  = ck / KKPOS;
            int kp = ck - c * KKPOS;
            int4 id = s_idx[kp * TN + n];
            const float* xp = xb + (size_t)c * HW;
            v[j * 4 + 0] = xp[id.x];
            v[j * 4 + 1] = xp[id.y];
            v[j * 4 + 2] = xp[id.z];
            v[j * 4 + 3] = xp[id.w];
        }
#pragma unroll
        for (int j = 0; j < 4; j++) {
            int ck = kb + kidx[j];
            int c  = ck / KKPOS;
            int kp = ck - c * KKPOS;
            float4 w = s_w[kp * TN + n];
            r[j] = w.x * v[j * 4 + 0] + w.y * v[j * 4 + 1]
                 + w.z * v[j * 4 + 2] + w.w * v[j * 4 + 3];
        }
        uint2 cell;
        cell.x = pack_h2(r[0], r[1]);
        cell.y = pack_h2(r[2], r[3]);
        sb[(ks16 * TN + n) * 4 + slot] = cell;
    }
}

__global__ __launch_bounds__(512, 1)
void gemm_fused_kernel(const float* __restrict__ x,
                       const float* __restrict__ bias,
                       float* __restrict__ out)
{
    extern __shared__ char smc[];
    char* sm = smc;
    const int tid = threadIdx.x;
    const int wid = tid >> 5;
    const int lid = tid & 31;
    const int g   = lid >> 2;
    const int t4  = lid & 3;
    const int wm  = wid & 3;
    const int wn  = wid >> 2;
    const int n0  = blockIdx.x * TN;
    const int b   = n0 >> 12;
    const int hw0 = n0 & 4095;
    const float* xb = x + (size_t)b * CIN * HW;

    int4*   s_idx = (int4*)  (sm + REC_BYTE_OFF);
    float4* s_w   = (float4*)(sm + REC_BYTE_OFF + 18432);

    for (int i = tid; i < KKPOS * TN; i += 512) {
        int kp = i >> 7, n = i & 127;
        int r  = ((b * KKPOS + kp) << 12) + hw0 + n;
        s_idx[i] = g_rec_idx[r];
        s_w[i]   = g_rec_w[r];
    }
    __syncthreads();

    float acc[4][4][4];
#pragma unroll
    for (int i = 0; i < 4; i++)
#pragma unroll
        for (int j = 0; j < 4; j++)
#pragma unroll
            for (int q = 0; q < 4; q++) acc[i][j][q] = 0.f;

    for (int pf = 0; pf < 2; pf++) {
        fill_A(sm, pf, pf, tid);
        fill_B(sm, pf, pf, tid, xb, s_idx, s_w);
    }

    for (int i = 0; i < KCHUNKS; i++) {
        const int s = i % NSTAGE;
        if (i == KCHUNKS - 1)
            asm volatile("cp.async.wait_group 0;" ::: "memory");
        else
            asm volatile("cp.async.wait_group 1;" ::: "memory");
        __syncthreads();

        if (i + 2 < KCHUNKS)
            fill_A(sm, (i + 2) % NSTAGE, i + 2, tid);

        const uint2* Au2 = (const uint2*)(sm + s * STAGE_BYTES);
        const uint2* Bu2 = (const uint2*)(sm + s * STAGE_BYTES + A_BYTES);

#pragma unroll
        for (int ks16 = 0; ks16 < 2; ks16++) {
            uint2 alo[4], ahi[4], bb[4];
#pragma unroll
            for (int ii = 0; ii < 4; ii++) {
                int m = wm * 64 + ii * 16 + g;
                alo[ii] = Au2[(ks16 * TM + m) * 4 + t4];
                ahi[ii] = Au2[(ks16 * TM + m + 8) * 4 + t4];
            }
#pragma unroll
            for (int jj = 0; jj < 4; jj++) {
                int n = wn * 32 + jj * 8 + g;
                bb[jj] = Bu2[(ks16 * TN + n) * 4 + ((t4 + (n >> 2)) & 3)];
            }
#pragma unroll
            for (int ii = 0; ii < 4; ii++)
#pragma unroll
                for (int jj = 0; jj < 4; jj++)
                    mma_f16(acc[ii][jj],
                            alo[ii].x, ahi[ii].x, alo[ii].y, ahi[ii].y,
                            bb[jj].x, bb[jj].y);
        }

        if (i + 2 < KCHUNKS)
            fill_B(sm, (i + 2) % NSTAGE, i + 2, tid, xb, s_idx, s_w);
    }

#pragma unroll
    for (int ii = 0; ii < 4; ii++) {
        int r0 = wm * 64 + ii * 16 + g;
        float bi0 = bias[r0], bi1 = bias[r0 + 8];
        float* p0 = out + ((size_t)(b * OUTC + r0)) * HW + hw0;
        float* p1 = p0 + (size_t)8 * HW;
#pragma unroll
        for (int jj = 0; jj < 4; jj++) {
            int col = wn * 32 + jj * 8 + 2 * t4;
            float2 v0 = make_float2(acc[ii][jj][0] + bi0, acc[ii][jj][1] + bi0);
            float2 v1 = make_float2(acc[ii][jj][2] + bi1, acc[ii][jj][3] + bi1);
            *(float2*)(p0 + col) = v0;
            *(float2*)(p1 + col) = v1;
        }
    }
}

// ---------------------------------------------------------------------------
// Launch: inputs per metadata order: x, w_off, b_off, weight, bias
// ---------------------------------------------------------------------------
extern "C" void kernel_launch(void* const* d_in, const int* in_sizes, int n_in,
                              void* d_out, int out_size)
{
    const float* x      = (const float*)d_in[0];
    const float* w_off  = (const float*)d_in[1];
    const float* b_off  = (const float*)d_in[2];
    const float* weight = (const float*)d_in[3];
    const float* bias   = (const float*)d_in[4];
    float* out = (float*)d_out;

    cudaFuncSetAttribute(gemm_fused_kernel,
                         cudaFuncAttributeMaxDynamicSharedMemorySize,
                         GEMM_SMEM_BYTES);
    cudaFuncSetAttribute(om_gemm_kernel,
                         cudaFuncAttributeMaxDynamicSharedMemorySize,
                         OM_SMEM_BYTES);

    wprep_kernel<<<(KCHUNKS * 2 * TM * 4 + 255) / 256, 256>>>(weight);
    wprep_off_kernel<<<(KCHUNKS * 2 * TM2 * 4 + 255) / 256, 256>>>(w_off);

    om_gemm_kernel<<<NPIX / TN2, 512, OM_SMEM_BYTES>>>(x, b_off);

    gemm_fused_kernel<<<NPIX / TN, 512, GEMM_SMEM_BYTES>>>(x, bias, out);
}

// round 14
// speedup vs baseline: 2.2572x; 1.0467x over previous
#include <cuda_runtime.h>
#include <cuda_fp16.h>
#include <cstdint>

// Problem constants
#define BATCH 4
#define CIN   256
#define HDIM  64
#define WDIM  64
#define HW    4096          // 64*64
#define OUTC  256
#define KKPOS 9             // 3x3
#define CKDIM 2304          // CIN * 9
#define NOFF  27            // 3*K*K offset-conv output channels
#define NPIX  (BATCH * HW)  // 16384
#define KS16TOT (CKDIM / 16)                  // 144 global k16 groups

// Fused GEMM config (mma.sync m16n8k16 fp16, fp32 accum), TK=64
#define TM 256
#define TN 128
#define TK 64
#define NSTAGE 3
#define KCHUNKS (CKDIM / TK)                  // 36
#define A_BYTES (4 * TM * 4 * 8)              // 32768 ([q16 0..3][m][t4] uint2)
#define B_BYTES (4 * TN * 4 * 8)              // 16384
#define STAGE_BYTES (A_BYTES + B_BYTES)       // 49152
#define REC_BYTE_OFF (NSTAGE * STAGE_BYTES)   // 147456
#define GEMM_SMEM_BYTES (REC_BYTE_OFF + 2 * 18432)   // 184320

// Offset-conv GEMM config (fp16, M=32 pad of 27, static im2col, fused rec)
#define TM2 32
#define TN2 128
#define A2_BYTES (4 * TM2 * 4 * 8)            // 4096
#define B2_BYTES (4 * TN2 * 4 * 8)            // 16384
#define STG2_BYTES (A2_BYTES + B2_BYTES)      // 20480
#define OM_SMEM_BYTES (NSTAGE * STG2_BYTES)   // 61440 (>= 16 KB som transpose)

__device__ __forceinline__ uint32_t smem_u32(const void* p) {
    uint32_t a;
    asm("{ .reg .u64 t; cvta.to.shared.u64 t, %1; cvt.u32.u64 %0, t; }" : "=r"(a) : "l"(p));
    return a;
}
__device__ __forceinline__ void cp16(uint32_t dst, const void* src) {
    asm volatile("cp.async.cg.shared.global [%0], [%1], 16;" :: "r"(dst), "l"(src));
}
__device__ __forceinline__ uint32_t pack_h2(float a, float b) {
    __half2 h = __floats2half2_rn(a, b);
    return *(uint32_t*)&h;
}
__device__ __forceinline__ void mma_f16(float* c,
                                        uint32_t a0, uint32_t a1, uint32_t a2, uint32_t a3,
                                        uint32_t b0, uint32_t b1) {
    asm volatile(
        "mma.sync.aligned.m16n8k16.row.col.f32.f16.f16.f32 "
        "{%0,%1,%2,%3}, {%4,%5,%6,%7}, {%8,%9}, {%0,%1,%2,%3};"
        : "+f"(c[0]), "+f"(c[1]), "+f"(c[2]), "+f"(c[3])
        : "r"(a0), "r"(a1), "r"(a2), "r"(a3), "r"(b0), "r"(b1));
}

// ---------------------------------------------------------------------------
// Scratch (static __device__ arrays)
// ---------------------------------------------------------------------------
__device__ int4   g_rec_idx[BATCH * KKPOS * HW];     // 2.36 MB
__device__ float4 g_rec_w  [BATCH * KKPOS * HW];     // 2.36 MB
// fp16 fragment-packed weights, flat in global ks16: [ks16][m][t4] uint2
__device__ uint2  g_wt2h[KS16TOT * TM * 4];          // 1.18 MB
__device__ uint2  g_woff2h[KS16TOT * TM2 * 4];       // 147 KB

// ---------------------------------------------------------------------------
// Kernel 0: pack BOTH weights to fp16 fragment layout (single launch).
// ---------------------------------------------------------------------------
#define WMAIN_ELEMS (KS16TOT * TM * 4)     // 147456
#define WOFF_ELEMS  (KS16TOT * TM2 * 4)    // 18432
__global__ __launch_bounds__(256)
void wprep_kernel(const float* __restrict__ weight,
                  const float* __restrict__ w_off)
{
    int i = blockIdx.x * 256 + threadIdx.x;
    if (i < WMAIN_ELEMS) {
        int t4   = i & 3;
        int m    = (i >> 2) & 255;
        int ks16 = i >> 10;
        int kb = ks16 * 16;
        const float* wr = weight + (size_t)m * CKDIM;
        uint2 v;
        v.x = pack_h2(wr[kb + 2 * t4],     wr[kb + 2 * t4 + 1]);
        v.y = pack_h2(wr[kb + 8 + 2 * t4], wr[kb + 8 + 2 * t4 + 1]);
        g_wt2h[i] = v;
    } else if (i < WMAIN_ELEMS + WOFF_ELEMS) {
        int j = i - WMAIN_ELEMS;
        int t4   = j & 3;
        int m    = (j >> 2) & 31;
        int ks16 = j >> 7;
        int kb = ks16 * 16;
        uint2 v;
        if (m < NOFF) {
            const float* wr = w_off + (size_t)m * CKDIM;
            v.x = pack_h2(wr[kb + 2 * t4],     wr[kb + 2 * t4 + 1]);
            v.y = pack_h2(wr[kb + 8 + 2 * t4], wr[kb + 8 + 2 * t4 + 1]);
        } else {
            v.x = 0u; v.y = 0u;
        }
        g_woff2h[j] = v;
    }
}

// ---------------------------------------------------------------------------
// Kernel 1: offset conv as fp16 MMA GEMM + FUSED record build. TK=64.
// 512 threads (16 warps, warp tile 16(M) x 16(N)), grid 128.
// ---------------------------------------------------------------------------
__device__ __forceinline__ void om_fill_A(char* sm, int stage, int chunk, int tid)
{
    if (tid < 256) {
        uint32_t sa = smem_u32(sm + stage * STG2_BYTES);
        const char* src = (const char*)(g_woff2h + (size_t)chunk * (4 * TM2 * 4));
        cp16(sa + (uint32_t)tid * 16, src + tid * 16);
    }
    asm volatile("cp.async.commit_group;" ::: "memory");
}

__device__ __forceinline__ void om_fill_B(char* sm, int stage, int chunk, int tid,
                                          const float* __restrict__ xb, int hw0)
{
    const int n   = tid & 127;
    const int t4q = tid >> 7;
    const int slot = (t4q + (n >> 2)) & 3;
    const int hw  = hw0 + n;
    const int y   = hw >> 6;
    const int xw  = hw & 63;
    uint2* sb = (uint2*)(sm + stage * STG2_BYTES + A2_BYTES);

#pragma unroll
    for (int q16 = 0; q16 < 4; q16++) {
        const int kb = chunk * TK + q16 * 16;
        const int kk0 = 2 * t4q;
        const int kidx[4] = { kk0, kk0 + 1, kk0 + 8, kk0 + 9 };
        float r[4];
#pragma unroll
        for (int j = 0; j < 4; j++) {
            int ck = kb + kidx[j];
            int c  = ck / KKPOS;
            int j9 = ck - c * KKPOS;
            int yy = y + j9 / 3 - 1;
            int xx = xw + j9 % 3 - 1;
            bool ok = (yy >= 0 && yy < HDIM && xx >= 0 && xx < WDIM);
            r[j] = ok ? xb[(size_t)c * HW + yy * WDIM + xx] : 0.f;
        }
        uint2 cell;
        cell.x = pack_h2(r[0], r[1]);
        cell.y = pack_h2(r[2], r[3]);
        sb[(q16 * TN2 + n) * 4 + slot] = cell;
    }
}

__global__ __launch_bounds__(512)
void om_gemm_kernel(const float* __restrict__ x,
                    const float* __restrict__ b_off)
{
    extern __shared__ char smc[];
    char* sm = smc;
    const int tid = threadIdx.x;
    const int wid = tid >> 5;
    const int lid = tid & 31;
    const int g   = lid >> 2;
    const int t4  = lid & 3;
    const int wm  = wid & 1;       // M half (16 rows)
    const int wn  = wid >> 1;      // N sixteenth (16 cols)
    const int n0  = blockIdx.x * TN2;
    const int b   = n0 >> 12;
    const int hw0 = n0 & 4095;
    const float* xb = x + (size_t)b * CIN * HW;

    float acc[2][4];
#pragma unroll
    for (int j = 0; j < 2; j++)
#pragma unroll
        for (int q = 0; q < 4; q++) acc[j][q] = 0.f;

    for (int pf = 0; pf < 2; pf++) {
        om_fill_A(sm, pf, pf, tid);
        om_fill_B(sm, pf, pf, tid, xb, hw0);
    }

    for (int i = 0; i < KCHUNKS; i++) {
        const int s = i % NSTAGE;
        if (i == KCHUNKS - 1)
            asm volatile("cp.async.wait_group 0;" ::: "memory");
        else
            asm volatile("cp.async.wait_group 1;" ::: "memory");
        __syncthreads();

        if (i + 2 < KCHUNKS)
            om_fill_A(sm, (i + 2) % NSTAGE, i + 2, tid);

        const uint2* Au2 = (const uint2*)(sm + s * STG2_BYTES);
        const uint2* Bu2 = (const uint2*)(sm + s * STG2_BYTES + A2_BYTES);

#pragma unroll
        for (int q16 = 0; q16 < 4; q16++) {
            int m = wm * 16 + g;
            uint2 alo = Au2[(q16 * TM2 + m) * 4 + t4];
            uint2 ahi = Au2[(q16 * TM2 + m + 8) * 4 + t4];
            uint2 bb[2];
#pragma unroll
            for (int jj = 0; jj < 2; jj++) {
                int n = wn * 16 + jj * 8 + g;
                bb[jj] = Bu2[(q16 * TN2 + n) * 4 + ((t4 + (n >> 2)) & 3)];
            }
#pragma unroll
            for (int jj = 0; jj < 2; jj++)
                mma_f16(acc[jj], alo.x, ahi.x, alo.y, ahi.y,
                        bb[jj].x, bb[jj].y);
        }

        if (i + 2 < KCHUNKS)
            om_fill_B(sm, (i + 2) % NSTAGE, i + 2, tid, xb, hw0);
    }

    // ---- Fused epilogue: transpose acc to som[32][128], then rec ----
    __syncthreads();
    float* som = (float*)sm;         // 16 KB

    {
        int ra = wm * 16 + g;
        int rb = ra + 8;
#pragma unroll
        for (int jj = 0; jj < 2; jj++) {
            int col = wn * 16 + jj * 8 + 2 * t4;
            *(float2*)&som[ra * TN2 + col] = make_float2(acc[jj][0], acc[jj][1]);
            *(float2*)&som[rb * TN2 + col] = make_float2(acc[jj][2], acc[jj][3]);
        }
    }
    __syncthreads();

    if (tid < TN2) {
        const int hw = hw0 + tid;
        const int y  = hw >> 6;
        const int xw = hw & 63;

        float a[NOFF];
#pragma unroll
        for (int oc = 0; oc < NOFF; oc++)
            a[oc] = b_off[oc] + som[oc * TN2 + tid];

#pragma unroll
        for (int kp = 0; kp < KKPOS; kp++) {
            float dy = a[2 * kp];
            float dx = a[2 * kp + 1];
            float mask = 1.f / (1.f + __expf(-a[18 + kp]));

            float py = (float)(y  - 1 + kp / 3) + dy;
            float px = (float)(xw - 1 + kp % 3) + dx;
            float y0f = floorf(py), x0f = floorf(px);
            float ly = py - y0f,   lx = px - x0f;
            int y0 = (int)y0f, x0 = (int)x0f;

            int4 idx; float4 wv;
            {
                int yy = y0, xx = x0;
                bool ok = (yy >= 0 && yy < HDIM && xx >= 0 && xx < WDIM);
                int yc = min(max(yy, 0), HDIM - 1), xc = min(max(xx, 0), WDIM - 1);
                idx.x = yc * WDIM + xc;
                wv.x = ok ? (1.f - ly) * (1.f - lx) * mask : 0.f;
            }
            {
                int yy = y0, xx = x0 + 1;
                bool ok = (yy >= 0 && yy < HDIM && xx >= 0 && xx < WDIM);
                int yc = min(max(yy, 0), HDIM - 1), xc = min(max(xx, 0), WDIM - 1);
                idx.y = yc * WDIM + xc;
                wv.y = ok ? (1.f - ly) * lx * mask : 0.f;
            }
            {
                int yy = y0 + 1, xx = x0;
                bool ok = (yy >= 0 && yy < HDIM && xx >= 0 && xx < WDIM);
                int yc = min(max(yy, 0), HDIM - 1), xc = min(max(xx, 0), WDIM - 1);
                idx.z = yc * WDIM + xc;
                wv.z = ok ? ly * (1.f - lx) * mask : 0.f;
            }
            {
                int yy = y0 + 1, xx = x0 + 1;
                bool ok = (yy >= 0 && yy < HDIM && xx >= 0 && xx < WDIM);
                int yc = min(max(yy, 0), HDIM - 1), xc = min(max(xx, 0), WDIM - 1);
                idx.w = yc * WDIM + xc;
                wv.w = ok ? ly * lx * mask : 0.f;
            }

            int r = ((b * KKPOS + kp) << 12) + hw;
            g_rec_idx[r] = idx;
            g_rec_w[r]   = wv;
        }
    }
}

// ---------------------------------------------------------------------------
// Kernel 2 (fused): gather + fp16 mma.sync GEMM. TK=64 (36 iterations).
// ---------------------------------------------------------------------------
__device__ __forceinline__ void fill_A(char* sm, int stage, int chunk, int tid)
{
    uint32_t sa = smem_u32(sm + stage * STAGE_BYTES);
    const char* src = (const char*)(g_wt2h + (size_t)chunk * (4 * TM * 4));
#pragma unroll
    for (int it = 0; it < 4; it++) {
        int c = tid + it * 512;
        cp16(sa + (uint32_t)c * 16, src + c * 16);
    }
    asm volatile("cp.async.commit_group;" ::: "memory");
}

__device__ __forceinline__ void fill_B(char* sm, int stage, int chunk, int tid,
                                       const float* __restrict__ xb,
                                       const int4* s_idx, const float4* s_w)
{
    const int n   = tid & 127;
    const int t4q = tid >> 7;
    const int slot = (t4q + (n >> 2)) & 3;
    uint2* sb = (uint2*)(sm + stage * STAGE_BYTES + A_BYTES);

#pragma unroll
    for (int q16 = 0; q16 < 4; q16++) {
        const int kb = chunk * TK + q16 * 16;
        const int kk0 = 2 * t4q;
        const int kidx[4] = { kk0, kk0 + 1, kk0 + 8, kk0 + 9 };
        float r[4];
        float v[16];
#pragma unroll
        for (int j = 0; j < 4; j++) {
            int ck = kb + kidx[j];
            int c  = ck / KKPOS;
            int kp = ck - c * KKPOS;
            int4 id = s_idx[kp * TN + n];
            const float* xp = xb + (size_t)c * HW;
            v[j * 4 + 0] = xp[id.x];
            v[j * 4 + 1] = xp[id.y];
            v[j * 4 + 2] = xp[id.z];
            v[j * 4 + 3] = xp[id.w];
        }
#pragma unroll
        for (int j = 0; j < 4; j++) {
            int ck = kb + kidx[j];
            int c  = ck / KKPOS;
            int kp = ck - c * KKPOS;
            float4 w = s_w[kp * TN + n];
            r[j] = w.x * v[j * 4 + 0] + w.y * v[j * 4 + 1]
                 + w.z * v[j * 4 + 2] + w.w * v[j * 4 + 3];
        }
        uint2 cell;
        cell.x = pack_h2(r[0], r[1]);
        cell.y = pack_h2(r[2], r[3]);
        sb[(q16 * TN + n) * 4 + slot] = cell;
    }
}

__global__ __launch_bounds__(512, 1)
void gemm_fused_kernel(const float* __restrict__ x,
                       const float* __restrict__ bias,
                       float* __restrict__ out)
{
    extern __shared__ char smc[];
    char* sm = smc;
    const int tid = threadIdx.x;
    const int wid = tid >> 5;
    const int lid = tid & 31;
    const int g   = lid >> 2;
    const int t4  = lid & 3;
    const int wm  = wid & 3;
    const int wn  = wid >> 2;
    const int n0  = blockIdx.x * TN;
    const int b   = n0 >> 12;
    const int hw0 = n0 & 4095;
    const float* xb = x + (size_t)b * CIN * HW;

    int4*   s_idx = (int4*)  (sm + REC_BYTE_OFF);
    float4* s_w   = (float4*)(sm + REC_BYTE_OFF + 18432);

    for (int i = tid; i < KKPOS * TN; i += 512) {
        int kp = i >> 7, n = i & 127;
        int r  = ((b * KKPOS + kp) << 12) + hw0 + n;
        s_idx[i] = g_rec_idx[r];
        s_w[i]   = g_rec_w[r];
    }
    __syncthreads();

    float acc[4][4][4];
#pragma unroll
    for (int i = 0; i < 4; i++)
#pragma unroll
        for (int j = 0; j < 4; j++)
#pragma unroll
            for (int q = 0; q < 4; q++) acc[i][j][q] = 0.f;

    for (int pf = 0; pf < 2; pf++) {
        fill_A(sm, pf, pf, tid);
        fill_B(sm, pf, pf, tid, xb, s_idx, s_w);
    }

    for (int i = 0; i < KCHUNKS; i++) {
        const int s = i % NSTAGE;
        if (i == KCHUNKS - 1)
            asm volatile("cp.async.wait_group 0;" ::: "memory");
        else
            asm volatile("cp.async.wait_group 1;" ::: "memory");
        __syncthreads();

        if (i + 2 < KCHUNKS)
            fill_A(sm, (i + 2) % NSTAGE, i + 2, tid);

        const uint2* Au2 = (const uint2*)(sm + s * STAGE_BYTES);
        const uint2* Bu2 = (const uint2*)(sm + s * STAGE_BYTES + A_BYTES);

#pragma unroll
        for (int q16 = 0; q16 < 4; q16++) {
            uint2 alo[4], ahi[4], bb[4];
#pragma unroll
            for (int ii = 0; ii < 4; ii++) {
                int m = wm * 64 + ii * 16 + g;
                alo[ii] = Au2[(q16 * TM + m) * 4 + t4];
                ahi[ii] = Au2[(q16 * TM + m + 8) * 4 + t4];
            }
#pragma unroll
            for (int jj = 0; jj < 4; jj++) {
                int n = wn * 32 + jj * 8 + g;
                bb[jj] = Bu2[(q16 * TN + n) * 4 + ((t4 + (n >> 2)) & 3)];
            }
#pragma unroll
            for (int ii = 0; ii < 4; ii++)
#pragma unroll
                for (int jj = 0; jj < 4; jj++)
                    mma_f16(acc[ii][jj],
                            alo[ii].x, ahi[ii].x, alo[ii].y, ahi[ii].y,
                            bb[jj].x, bb[jj].y);
        }

        if (i + 2 < KCHUNKS)
            fill_B(sm, (i + 2) % NSTAGE, i + 2, tid, xb, s_idx, s_w);
    }

#pragma unroll
    for (int ii = 0; ii < 4; ii++) {
        int r0 = wm * 64 + ii * 16 + g;
        float bi0 = bias[r0], bi1 = bias[r0 + 8];
        float* p0 = out + ((size_t)(b * OUTC + r0)) * HW + hw0;
        float* p1 = p0 + (size_t)8 * HW;
#pragma unroll
        for (int jj = 0; jj < 4; jj++) {
            int col = wn * 32 + jj * 8 + 2 * t4;
            float2 v0 = make_float2(acc[ii][jj][0] + bi0, acc[ii][jj][1] + bi0);
            float2 v1 = make_float2(acc[ii][jj][2] + bi1, acc[ii][jj][3] + bi1);
            *(float2*)(p0 + col) = v0;
            *(float2*)(p1 + col) = v1;
        }
    }
}

// ---------------------------------------------------------------------------
// Launch: inputs per metadata order: x, w_off, b_off, weight, bias
// ---------------------------------------------------------------------------
extern "C" void kernel_launch(void* const* d_in, const int* in_sizes, int n_in,
                              void* d_out, int out_size)
{
    const float* x      = (const float*)d_in[0];
    const float* w_off  = (const float*)d_in[1];
    const float* b_off  = (const float*)d_in[2];
    const float* weight = (const float*)d_in[3];
    const float* bias   = (const float*)d_in[4];
    float* out = (float*)d_out;

    cudaFuncSetAttribute(gemm_fused_kernel,
                         cudaFuncAttributeMaxDynamicSharedMemorySize,
                         GEMM_SMEM_BYTES);
    cudaFuncSetAttribute(om_gemm_kernel,
                         cudaFuncAttributeMaxDynamicSharedMemorySize,
                         OM_SMEM_BYTES);

    wprep_kernel<<<(WMAIN_ELEMS + WOFF_ELEMS + 255) / 256, 256>>>(weight, w_off);

    om_gemm_kernel<<<NPIX / TN2, 512, OM_SMEM_BYTES>>>(x, b_off);

    gemm_fused_kernel<<<NPIX / TN, 512, GEMM_SMEM_BYTES>>>(x, bias, out);
}

// round 15
// speedup vs baseline: 2.3912x; 1.0594x over previous
#include <cuda_runtime.h>
#include <cuda_fp16.h>
#include <cstdint>

// Problem constants
#define BATCH 4
#define CIN   256
#define HDIM  64
#define WDIM  64
#define HW    4096          // 64*64
#define OUTC  256
#define KKPOS 9             // 3x3
#define CKDIM 2304          // CIN * 9
#define NOFF  27            // 3*K*K offset-conv output channels
#define NPIX  (BATCH * HW)  // 16384
#define KS16TOT (CKDIM / 16)                  // 144 global k16 groups

// Fused GEMM config (mma.sync m16n8k16 fp16, fp32 accum), TK=128, 2 stages
#define TM 256
#define TN 128
#define TK 128
#define NQ16 (TK / 16)                        // 8
#define NSTAGE 2
#define KCHUNKS (CKDIM / TK)                  // 18
#define A_BYTES (NQ16 * TM * 4 * 8)           // 65536 ([q16][m][t4] uint2)
#define B_BYTES (NQ16 * TN * 4 * 8)           // 32768
#define STAGE_BYTES (A_BYTES + B_BYTES)       // 98304
#define REC_BYTE_OFF (NSTAGE * STAGE_BYTES)   // 196608
// records: 1152 ushort4 (9216 B) + 1152 float4 (18432 B)
#define GEMM_SMEM_BYTES (REC_BYTE_OFF + 9216 + 18432)   // 224256

// Offset-conv GEMM config (fp16, M=32 pad of 27, static im2col, fused rec)
#define TM2 32
#define TN2 128
#define A2_BYTES (NQ16 * TM2 * 4 * 8)         // 8192
#define B2_BYTES (NQ16 * TN2 * 4 * 8)         // 32768
#define STG2_BYTES (A2_BYTES + B2_BYTES)      // 40960
#define OM_SMEM_BYTES (NSTAGE * STG2_BYTES)   // 81920 (>= 16 KB som transpose)

__device__ __forceinline__ uint32_t smem_u32(const void* p) {
    uint32_t a;
    asm("{ .reg .u64 t; cvta.to.shared.u64 t, %1; cvt.u32.u64 %0, t; }" : "=r"(a) : "l"(p));
    return a;
}
__device__ __forceinline__ void cp16(uint32_t dst, const void* src) {
    asm volatile("cp.async.cg.shared.global [%0], [%1], 16;" :: "r"(dst), "l"(src));
}
__device__ __forceinline__ uint32_t pack_h2(float a, float b) {
    __half2 h = __floats2half2_rn(a, b);
    return *(uint32_t*)&h;
}
__device__ __forceinline__ void mma_f16(float* c,
                                        uint32_t a0, uint32_t a1, uint32_t a2, uint32_t a3,
                                        uint32_t b0, uint32_t b1) {
    asm volatile(
        "mma.sync.aligned.m16n8k16.row.col.f32.f16.f16.f32 "
        "{%0,%1,%2,%3}, {%4,%5,%6,%7}, {%8,%9}, {%0,%1,%2,%3};"
        : "+f"(c[0]), "+f"(c[1]), "+f"(c[2]), "+f"(c[3])
        : "r"(a0), "r"(a1), "r"(a2), "r"(a3), "r"(b0), "r"(b1));
}

// ---------------------------------------------------------------------------
// Scratch (static __device__ arrays)
// ---------------------------------------------------------------------------
__device__ int4   g_rec_idx[BATCH * KKPOS * HW];     // 2.36 MB
__device__ float4 g_rec_w  [BATCH * KKPOS * HW];     // 2.36 MB
// fp16 fragment-packed weights, flat in global ks16: [ks16][m][t4] uint2
__device__ uint2  g_wt2h[KS16TOT * TM * 4];          // 1.18 MB
__device__ uint2  g_woff2h[KS16TOT * TM2 * 4];       // 147 KB

// ---------------------------------------------------------------------------
// Kernel 0: pack BOTH weights to fp16 fragment layout (single launch).
// ---------------------------------------------------------------------------
#define WMAIN_ELEMS (KS16TOT * TM * 4)     // 147456
#define WOFF_ELEMS  (KS16TOT * TM2 * 4)    // 18432
__global__ __launch_bounds__(256)
void wprep_kernel(const float* __restrict__ weight,
                  const float* __restrict__ w_off)
{
    int i = blockIdx.x * 256 + threadIdx.x;
    if (i < WMAIN_ELEMS) {
        int t4   = i & 3;
        int m    = (i >> 2) & 255;
        int ks16 = i >> 10;
        int kb = ks16 * 16;
        const float* wr = weight + (size_t)m * CKDIM;
        uint2 v;
        v.x = pack_h2(wr[kb + 2 * t4],     wr[kb + 2 * t4 + 1]);
        v.y = pack_h2(wr[kb + 8 + 2 * t4], wr[kb + 8 + 2 * t4 + 1]);
        g_wt2h[i] = v;
    } else if (i < WMAIN_ELEMS + WOFF_ELEMS) {
        int j = i - WMAIN_ELEMS;
        int t4   = j & 3;
        int m    = (j >> 2) & 31;
        int ks16 = j >> 7;
        int kb = ks16 * 16;
        uint2 v;
        if (m < NOFF) {
            const float* wr = w_off + (size_t)m * CKDIM;
            v.x = pack_h2(wr[kb + 2 * t4],     wr[kb + 2 * t4 + 1]);
            v.y = pack_h2(wr[kb + 8 + 2 * t4], wr[kb + 8 + 2 * t4 + 1]);
        } else {
            v.x = 0u; v.y = 0u;
        }
        g_woff2h[j] = v;
    }
}

// ---------------------------------------------------------------------------
// Kernel 1: offset conv as fp16 MMA GEMM + FUSED record build. TK=128.
// 512 threads (16 warps, warp tile 16(M) x 16(N)), grid 128, 2 stages.
// ---------------------------------------------------------------------------
__device__ __forceinline__ void om_fill_A(char* sm, int stage, int chunk, int tid)
{
    uint32_t sa = smem_u32(sm + stage * STG2_BYTES);
    const char* src = (const char*)(g_woff2h + (size_t)chunk * (NQ16 * TM2 * 4));
    cp16(sa + (uint32_t)tid * 16, src + tid * 16);   // 512 cp16, 1 per thread
    asm volatile("cp.async.commit_group;" ::: "memory");
}

__device__ __forceinline__ void om_fill_B(char* sm, int stage, int chunk, int tid,
                                          const float* __restrict__ xb, int hw0)
{
    const int n   = tid & 127;
    const int t4q = tid >> 7;
    const int slot = (t4q + (n >> 2)) & 3;
    const int hw  = hw0 + n;
    const int y   = hw >> 6;
    const int xw  = hw & 63;
    uint2* sb = (uint2*)(sm + stage * STG2_BYTES + A2_BYTES);

#pragma unroll
    for (int q16 = 0; q16 < NQ16; q16++) {
        const int kb = chunk * TK + q16 * 16;
        const int kk0 = 2 * t4q;
        const int kidx[4] = { kk0, kk0 + 1, kk0 + 8, kk0 + 9 };
        float r[4];
#pragma unroll
        for (int j = 0; j < 4; j++) {
            int ck = kb + kidx[j];
            int c  = ck / KKPOS;
            int j9 = ck - c * KKPOS;
            int yy = y + j9 / 3 - 1;
            int xx = xw + j9 % 3 - 1;
            bool ok = (yy >= 0 && yy < HDIM && xx >= 0 && xx < WDIM);
            r[j] = ok ? xb[(size_t)c * HW + yy * WDIM + xx] : 0.f;
        }
        uint2 cell;
        cell.x = pack_h2(r[0], r[1]);
        cell.y = pack_h2(r[2], r[3]);
        sb[(q16 * TN2 + n) * 4 + slot] = cell;
    }
}

__global__ __launch_bounds__(512)
void om_gemm_kernel(const float* __restrict__ x,
                    const float* __restrict__ b_off)
{
    extern __shared__ char smc[];
    char* sm = smc;
    const int tid = threadIdx.x;
    const int wid = tid >> 5;
    const int lid = tid & 31;
    const int g   = lid >> 2;
    const int t4  = lid & 3;
    const int wm  = wid & 1;       // M half (16 rows)
    const int wn  = wid >> 1;      // N sixteenth (16 cols)
    const int n0  = blockIdx.x * TN2;
    const int b   = n0 >> 12;
    const int hw0 = n0 & 4095;
    const float* xb = x + (size_t)b * CIN * HW;

    float acc[2][4];
#pragma unroll
    for (int j = 0; j < 2; j++)
#pragma unroll
        for (int q = 0; q < 4; q++) acc[j][q] = 0.f;

    om_fill_A(sm, 0, 0, tid);
    om_fill_B(sm, 0, 0, tid, xb, hw0);

    for (int i = 0; i < KCHUNKS; i++) {
        const int s = i & 1;
        asm volatile("cp.async.wait_group 0;" ::: "memory");
        __syncthreads();

        if (i + 1 < KCHUNKS)
            om_fill_A(sm, s ^ 1, i + 1, tid);

        const uint2* Au2 = (const uint2*)(sm + s * STG2_BYTES);
        const uint2* Bu2 = (const uint2*)(sm + s * STG2_BYTES + A2_BYTES);

#pragma unroll
        for (int q16 = 0; q16 < NQ16; q16++) {
            int m = wm * 16 + g;
            uint2 alo = Au2[(q16 * TM2 + m) * 4 + t4];
            uint2 ahi = Au2[(q16 * TM2 + m + 8) * 4 + t4];
            uint2 bb[2];
#pragma unroll
            for (int jj = 0; jj < 2; jj++) {
                int n = wn * 16 + jj * 8 + g;
                bb[jj] = Bu2[(q16 * TN2 + n) * 4 + ((t4 + (n >> 2)) & 3)];
            }
#pragma unroll
            for (int jj = 0; jj < 2; jj++)
                mma_f16(acc[jj], alo.x, ahi.x, alo.y, ahi.y,
                        bb[jj].x, bb[jj].y);
        }

        if (i + 1 < KCHUNKS)
            om_fill_B(sm, s ^ 1, i + 1, tid, xb, hw0);
    }

    // ---- Fused epilogue: transpose acc to som[32][128], then rec ----
    __syncthreads();
    float* som = (float*)sm;         // 16 KB

    {
        int ra = wm * 16 + g;
        int rb = ra + 8;
#pragma unroll
        for (int jj = 0; jj < 2; jj++) {
            int col = wn * 16 + jj * 8 + 2 * t4;
            *(float2*)&som[ra * TN2 + col] = make_float2(acc[jj][0], acc[jj][1]);
            *(float2*)&som[rb * TN2 + col] = make_float2(acc[jj][2], acc[jj][3]);
        }
    }
    __syncthreads();

    if (tid < TN2) {
        const int hw = hw0 + tid;
        const int y  = hw >> 6;
        const int xw = hw & 63;

        float a[NOFF];
#pragma unroll
        for (int oc = 0; oc < NOFF; oc++)
            a[oc] = b_off[oc] + som[oc * TN2 + tid];

#pragma unroll
        for (int kp = 0; kp < KKPOS; kp++) {
            float dy = a[2 * kp];
            float dx = a[2 * kp + 1];
            float mask = 1.f / (1.f + __expf(-a[18 + kp]));

            float py = (float)(y  - 1 + kp / 3) + dy;
            float px = (float)(xw - 1 + kp % 3) + dx;
            float y0f = floorf(py), x0f = floorf(px);
            float ly = py - y0f,   lx = px - x0f;
            int y0 = (int)y0f, x0 = (int)x0f;

            int4 idx; float4 wv;
            {
                int yy = y0, xx = x0;
                bool ok = (yy >= 0 && yy < HDIM && xx >= 0 && xx < WDIM);
                int yc = min(max(yy, 0), HDIM - 1), xc = min(max(xx, 0), WDIM - 1);
                idx.x = yc * WDIM + xc;
                wv.x = ok ? (1.f - ly) * (1.f - lx) * mask : 0.f;
            }
            {
                int yy = y0, xx = x0 + 1;
                bool ok = (yy >= 0 && yy < HDIM && xx >= 0 && xx < WDIM);
                int yc = min(max(yy, 0), HDIM - 1), xc = min(max(xx, 0), WDIM - 1);
                idx.y = yc * WDIM + xc;
                wv.y = ok ? (1.f - ly) * lx * mask : 0.f;
            }
            {
                int yy = y0 + 1, xx = x0;
                bool ok = (yy >= 0 && yy < HDIM && xx >= 0 && xx < WDIM);
                int yc = min(max(yy, 0), HDIM - 1), xc = min(max(xx, 0), WDIM - 1);
                idx.z = yc * WDIM + xc;
                wv.z = ok ? ly * (1.f - lx) * mask : 0.f;
            }
            {
                int yy = y0 + 1, xx = x0 + 1;
                bool ok = (yy >= 0 && yy < HDIM && xx >= 0 && xx < WDIM);
                int yc = min(max(yy, 0), HDIM - 1), xc = min(max(xx, 0), WDIM - 1);
                idx.w = yc * WDIM + xc;
                wv.w = ok ? ly * lx * mask : 0.f;
            }

            int r = ((b * KKPOS + kp) << 12) + hw;
            g_rec_idx[r] = idx;
            g_rec_w[r]   = wv;
        }
    }
}

// ---------------------------------------------------------------------------
// Kernel 2 (fused): gather + fp16 mma.sync GEMM. TK=128 (18 iterations),
// 2 stages, records in smem as ushort4 idx + float4 weights.
// ---------------------------------------------------------------------------
__device__ __forceinline__ void fill_A(char* sm, int stage, int chunk, int tid)
{
    uint32_t sa = smem_u32(sm + stage * STAGE_BYTES);
    const char* src = (const char*)(g_wt2h + (size_t)chunk * (NQ16 * TM * 4));
#pragma unroll
    for (int it = 0; it < 8; it++) {
        int c = tid + it * 512;
        cp16(sa + (uint32_t)c * 16, src + c * 16);
    }
    asm volatile("cp.async.commit_group;" ::: "memory");
}

__device__ __forceinline__ void fill_B(char* sm, int stage, int chunk, int tid,
                                       const float* __restrict__ xb,
                                       const ushort4* s_idx, const float4* s_w)
{
    const int n   = tid & 127;
    const int t4q = tid >> 7;
    const int slot = (t4q + (n >> 2)) & 3;
    uint2* sb = (uint2*)(sm + stage * STAGE_BYTES + A_BYTES);

#pragma unroll
    for (int q16 = 0; q16 < NQ16; q16++) {
        const int kb = chunk * TK + q16 * 16;
        const int kk0 = 2 * t4q;
        const int kidx[4] = { kk0, kk0 + 1, kk0 + 8, kk0 + 9 };
        float r[4];
        float v[16];
#pragma unroll
        for (int j = 0; j < 4; j++) {
            int ck = kb + kidx[j];
            int c  = ck / KKPOS;
            int kp = ck - c * KKPOS;
            ushort4 id = s_idx[kp * TN + n];
            const float* xp = xb + (size_t)c * HW;
            v[j * 4 + 0] = xp[id.x];
            v[j * 4 + 1] = xp[id.y];
            v[j * 4 + 2] = xp[id.z];
            v[j * 4 + 3] = xp[id.w];
        }
#pragma unroll
        for (int j = 0; j < 4; j++) {
            int ck = kb + kidx[j];
            int c  = ck / KKPOS;
            int kp = ck - c * KKPOS;
            float4 w = s_w[kp * TN + n];
            r[j] = w.x * v[j * 4 + 0] + w.y * v[j * 4 + 1]
                 + w.z * v[j * 4 + 2] + w.w * v[j * 4 + 3];
        }
        uint2 cell;
        cell.x = pack_h2(r[0], r[1]);
        cell.y = pack_h2(r[2], r[3]);
        sb[(q16 * TN + n) * 4 + slot] = cell;
    }
}

__global__ __launch_bounds__(512, 1)
void gemm_fused_kernel(const float* __restrict__ x,
                       const float* __restrict__ bias,
                       float* __restrict__ out)
{
    extern __shared__ char smc[];
    char* sm = smc;
    const int tid = threadIdx.x;
    const int wid = tid >> 5;
    const int lid = tid & 31;
    const int g   = lid >> 2;
    const int t4  = lid & 3;
    const int wm  = wid & 3;
    const int wn  = wid >> 2;
    const int n0  = blockIdx.x * TN;
    const int b   = n0 >> 12;
    const int hw0 = n0 & 4095;
    const float* xb = x + (size_t)b * CIN * HW;

    ushort4* s_idx = (ushort4*)(sm + REC_BYTE_OFF);
    float4*  s_w   = (float4*) (sm + REC_BYTE_OFF + 9216);

    for (int i = tid; i < KKPOS * TN; i += 512) {
        int kp = i >> 7, n = i & 127;
        int r  = ((b * KKPOS + kp) << 12) + hw0 + n;
        int4 id = g_rec_idx[r];
        s_idx[i] = make_ushort4((unsigned short)id.x, (unsigned short)id.y,
                                (unsigned short)id.z, (unsigned short)id.w);
        s_w[i]   = g_rec_w[r];
    }
    __syncthreads();

    float acc[4][4][4];
#pragma unroll
    for (int i = 0; i < 4; i++)
#pragma unroll
        for (int j = 0; j < 4; j++)
#pragma unroll
            for (int q = 0; q < 4; q++) acc[i][j][q] = 0.f;

    fill_A(sm, 0, 0, tid);
    fill_B(sm, 0, 0, tid, xb, s_idx, s_w);

    for (int i = 0; i < KCHUNKS; i++) {
        const int s = i & 1;
        asm volatile("cp.async.wait_group 0;" ::: "memory");
        __syncthreads();   // publishes B(i), frees stage s^1

        if (i + 1 < KCHUNKS)
            fill_A(sm, s ^ 1, i + 1, tid);

        const uint2* Au2 = (const uint2*)(sm + s * STAGE_BYTES);
        const uint2* Bu2 = (const uint2*)(sm + s * STAGE_BYTES + A_BYTES);

#pragma unroll
        for (int q16 = 0; q16 < NQ16; q16++) {
            uint2 alo[4], ahi[4], bb[4];
#pragma unroll
            for (int ii = 0; ii < 4; ii++) {
                int m = wm * 64 + ii * 16 + g;
                alo[ii] = Au2[(q16 * TM + m) * 4 + t4];
                ahi[ii] = Au2[(q16 * TM + m + 8) * 4 + t4];
            }
#pragma unroll
            for (int jj = 0; jj < 4; jj++) {
                int n = wn * 32 + jj * 8 + g;
                bb[jj] = Bu2[(q16 * TN + n) * 4 + ((t4 + (n >> 2)) & 3)];
            }
#pragma unroll
            for (int ii = 0; ii < 4; ii++)
#pragma unroll
                for (int jj = 0; jj < 4; jj++)
                    mma_f16(acc[ii][jj],
                            alo[ii].x, ahi[ii].x, alo[ii].y, ahi[ii].y,
                            bb[jj].x, bb[jj].y);
        }

        if (i + 1 < KCHUNKS)
            fill_B(sm, s ^ 1, i + 1, tid, xb, s_idx, s_w);
    }

#pragma unroll
    for (int ii = 0; ii < 4; ii++) {
        int r0 = wm * 64 + ii * 16 + g;
        float bi0 = bias[r0], bi1 = bias[r0 + 8];
        float* p0 = out + ((size_t)(b * OUTC + r0)) * HW + hw0;
        float* p1 = p0 + (size_t)8 * HW;
#pragma unroll
        for (int jj = 0; jj < 4; jj++) {
            int col = wn * 32 + jj * 8 + 2 * t4;
            float2 v0 = make_float2(acc[ii][jj][0] + bi0, acc[ii][jj][1] + bi0);
            float2 v1 = make_float2(acc[ii][jj][2] + bi1, acc[ii][jj][3] + bi1);
            *(float2*)(p0 + col) = v0;
            *(float2*)(p1 + col) = v1;
        }
    }
}

// ---------------------------------------------------------------------------
// Launch: inputs per metadata order: x, w_off, b_off, weight, bias
// ---------------------------------------------------------------------------
extern "C" void kernel_launch(void* const* d_in, const int* in_sizes, int n_in,
                              void* d_out, int out_size)
{
    const float* x      = (const float*)d_in[0];
    const float* w_off  = (const float*)d_in[1];
    const float* b_off  = (const float*)d_in[2];
    const float* weight = (const float*)d_in[3];
    const float* bias   = (const float*)d_in[4];
    float* out = (float*)d_out;

    cudaFuncSetAttribute(gemm_fused_kernel,
                         cudaFuncAttributeMaxDynamicSharedMemorySize,
                         GEMM_SMEM_BYTES);
    cudaFuncSetAttribute(om_gemm_kernel,
                         cudaFuncAttributeMaxDynamicSharedMemorySize,
                         OM_SMEM_BYTES);

    wprep_kernel<<<(WMAIN_ELEMS + WOFF_ELEMS + 255) / 256, 256>>>(weight, w_off);

    om_gemm_kernel<<<NPIX / TN2, 512, OM_SMEM_BYTES>>>(x, b_off);

    gemm_fused_kernel<<<NPIX / TN, 512, GEMM_SMEM_BYTES>>>(x, bias, out);
}

// round 17
// speedup vs baseline: 2.4450x; 1.0225x over previous
#include <cuda_runtime.h>
#include <cuda_fp16.h>
#include <cstdint>

// Problem constants
#define BATCH 4
#define CIN   256
#define HDIM  64
#define WDIM  64
#define HW    4096          // 64*64
#define OUTC  256
#define KKPOS 9             // 3x3
#define CKDIM 2304          // CIN * 9
#define NOFF  27            // 3*K*K offset-conv output channels
#define NPIX  (BATCH * HW)  // 16384
#define KS16TOT (CKDIM / 16)                  // 144 global k16 groups

// Main GEMM config (mma.sync m16n8k16 fp16, fp32 accum), TK=128, 2 stages
#define TM 256
#define TN 128
#define TK 128
#define NQ16 (TK / 16)                        // 8
#define NSTAGE 2
#define KCHUNKS (CKDIM / TK)                  // 18
#define A_BYTES (NQ16 * TM * 4 * 8)           // 65536 ([q16][m][t4] uint2)
#define B_BYTES (NQ16 * TN * 4 * 8)           // 32768
#define STAGE_BYTES (A_BYTES + B_BYTES)       // 98304
#define REC_BYTE_OFF (NSTAGE * STAGE_BYTES)   // 196608
// records: 1152 ushort4 (9216 B) + 1152 float4 (18432 B)
#define MEGA_SMEM_BYTES (REC_BYTE_OFF + 9216 + 18432)   // 224256

// Offset-conv phase config (fp16, M=32 pad of 27, static im2col)
#define TM2 32
#define TN2 128
#define A2_BYTES (NQ16 * TM2 * 4 * 8)         // 8192
#define B2_BYTES (NQ16 * TN2 * 4 * 8)         // 32768
#define STG2_BYTES (A2_BYTES + B2_BYTES)      // 40960 (2 stages = 80 KB < 192 KB)

__device__ __forceinline__ uint32_t smem_u32(const void* p) {
    uint32_t a;
    asm("{ .reg .u64 t; cvta.to.shared.u64 t, %1; cvt.u32.u64 %0, t; }" : "=r"(a) : "l"(p));
    return a;
}
__device__ __forceinline__ void cp16(uint32_t dst, const void* src) {
    asm volatile("cp.async.cg.shared.global [%0], [%1], 16;" :: "r"(dst), "l"(src));
}
__device__ __forceinline__ uint32_t pack_h2(float a, float b) {
    __half2 h = __floats2half2_rn(a, b);
    return *(uint32_t*)&h;
}
__device__ __forceinline__ void mma_f16(float* c,
                                        uint32_t a0, uint32_t a1, uint32_t a2, uint32_t a3,
                                        uint32_t b0, uint32_t b1) {
    asm volatile(
        "mma.sync.aligned.m16n8k16.row.col.f32.f16.f16.f32 "
        "{%0,%1,%2,%3}, {%4,%5,%6,%7}, {%8,%9}, {%0,%1,%2,%3};"
        : "+f"(c[0]), "+f"(c[1]), "+f"(c[2]), "+f"(c[3])
        : "r"(a0), "r"(a1), "r"(a2), "r"(a3), "r"(b0), "r"(b1));
}

// ---------------------------------------------------------------------------
// Scratch: only packed weights remain in global memory.
// ---------------------------------------------------------------------------
__device__ uint2  g_wt2h[KS16TOT * TM * 4];          // 1.18 MB
__device__ uint2  g_woff2h[KS16TOT * TM2 * 4];       // 147 KB

// ---------------------------------------------------------------------------
// Kernel 0: pack BOTH weights to fp16 fragment layout (single launch).
// ---------------------------------------------------------------------------
#define WMAIN_ELEMS (KS16TOT * TM * 4)     // 147456
#define WOFF_ELEMS  (KS16TOT * TM2 * 4)    // 18432
__global__ __launch_bounds__(256)
void wprep_kernel(const float* __restrict__ weight,
                  const float* __restrict__ w_off)
{
    int i = blockIdx.x * 256 + threadIdx.x;
    if (i < WMAIN_ELEMS) {
        int t4   = i & 3;
        int m    = (i >> 2) & 255;
        int ks16 = i >> 10;
        int kb = ks16 * 16;
        const float* wr = weight + (size_t)m * CKDIM;
        uint2 v;
        v.x = pack_h2(wr[kb + 2 * t4],     wr[kb + 2 * t4 + 1]);
        v.y = pack_h2(wr[kb + 8 + 2 * t4], wr[kb + 8 + 2 * t4 + 1]);
        g_wt2h[i] = v;
    } else if (i < WMAIN_ELEMS + WOFF_ELEMS) {
        int j = i - WMAIN_ELEMS;
        int t4   = j & 3;
        int m    = (j >> 2) & 31;
        int ks16 = j >> 7;
        int kb = ks16 * 16;
        uint2 v;
        if (m < NOFF) {
            const float* wr = w_off + (size_t)m * CKDIM;
            v.x = pack_h2(wr[kb + 2 * t4],     wr[kb + 2 * t4 + 1]);
            v.y = pack_h2(wr[kb + 8 + 2 * t4], wr[kb + 8 + 2 * t4 + 1]);
        } else {
            v.x = 0u; v.y = 0u;
        }
        g_woff2h[j] = v;
    }
}

// ---------------------------------------------------------------------------
// Phase-1 helpers: offset-conv GEMM fill (static im2col).
// ---------------------------------------------------------------------------
__device__ __forceinline__ void om_fill_A(char* sm, int stage, int chunk, int tid)
{
    uint32_t sa = smem_u32(sm + stage * STG2_BYTES);
    const char* src = (const char*)(g_woff2h + (size_t)chunk * (NQ16 * TM2 * 4));
    cp16(sa + (uint32_t)tid * 16, src + tid * 16);   // 512 cp16, 1 per thread
    asm volatile("cp.async.commit_group;" ::: "memory");
}

__device__ __forceinline__ void om_fill_B(char* sm, int stage, int chunk, int tid,
                                          const float* __restrict__ xb, int hw0)
{
    const int n   = tid & 127;
    const int t4q = tid >> 7;
    const int slot = (t4q + (n >> 2)) & 3;
    const int hw  = hw0 + n;
    const int y   = hw >> 6;
    const int xw  = hw & 63;
    uint2* sb = (uint2*)(sm + stage * STG2_BYTES + A2_BYTES);

#pragma unroll
    for (int q16 = 0; q16 < NQ16; q16++) {
        const int kb = chunk * TK + q16 * 16;
        const int kk0 = 2 * t4q;
        const int kidx[4] = { kk0, kk0 + 1, kk0 + 8, kk0 + 9 };
        float r[4];
#pragma unroll
        for (int j = 0; j < 4; j++) {
            int ck = kb + kidx[j];
            int c  = ck / KKPOS;
            int j9 = ck - c * KKPOS;
            int yy = y + j9 / 3 - 1;
            int xx = xw + j9 % 3 - 1;
            bool ok = (yy >= 0 && yy < HDIM && xx >= 0 && xx < WDIM);
            r[j] = ok ? xb[(size_t)c * HW + yy * WDIM + xx] : 0.f;
        }
        uint2 cell;
        cell.x = pack_h2(r[0], r[1]);
        cell.y = pack_h2(r[2], r[3]);
        sb[(q16 * TN2 + n) * 4 + slot] = cell;
    }
}

// ---------------------------------------------------------------------------
// Phase-2 helpers: main GEMM fill (deformable gather via smem records).
// ---------------------------------------------------------------------------
__device__ __forceinline__ void fill_A(char* sm, int stage, int chunk, int tid)
{
    uint32_t sa = smem_u32(sm + stage * STAGE_BYTES);
    const char* src = (const char*)(g_wt2h + (size_t)chunk * (NQ16 * TM * 4));
#pragma unroll
    for (int it = 0; it < 8; it++) {
        int c = tid + it * 512;
        cp16(sa + (uint32_t)c * 16, src + c * 16);
    }
    asm volatile("cp.async.commit_group;" ::: "memory");
}

__device__ __forceinline__ void fill_B(char* sm, int stage, int chunk, int tid,
                                       const float* __restrict__ xb,
                                       const ushort4* s_idx, const float4* s_w)
{
    const int n   = tid & 127;
    const int t4q = tid >> 7;
    const int slot = (t4q + (n >> 2)) & 3;
    uint2* sb = (uint2*)(sm + stage * STAGE_BYTES + A_BYTES);

#pragma unroll
    for (int q16 = 0; q16 < NQ16; q16++) {
        const int kb = chunk * TK + q16 * 16;
        const int kk0 = 2 * t4q;
        const int kidx[4] = { kk0, kk0 + 1, kk0 + 8, kk0 + 9 };
        float r[4];
        float v[16];
#pragma unroll
        for (int j = 0; j < 4; j++) {
            int ck = kb + kidx[j];
            int c  = ck / KKPOS;
            int kp = ck - c * KKPOS;
            ushort4 id = s_idx[kp * TN + n];
            const float* xp = xb + (size_t)c * HW;
            v[j * 4 + 0] = xp[id.x];
            v[j * 4 + 1] = xp[id.y];
            v[j * 4 + 2] = xp[id.z];
            v[j * 4 + 3] = xp[id.w];
        }
#pragma unroll
        for (int j = 0; j < 4; j++) {
            int ck = kb + kidx[j];
            int c  = ck / KKPOS;
            int kp = ck - c * KKPOS;
            float4 w = s_w[kp * TN + n];
            r[j] = w.x * v[j * 4 + 0] + w.y * v[j * 4 + 1]
                 + w.z * v[j * 4 + 2] + w.w * v[j * 4 + 3];
        }
        uint2 cell;
        cell.x = pack_h2(r[0], r[1]);
        cell.y = pack_h2(r[2], r[3]);
        sb[(q16 * TN + n) * 4 + slot] = cell;
    }
}

// ---------------------------------------------------------------------------
// MEGA kernel: phase 1 (offset conv + records) then phase 2 (main GEMM).
// One CTA owns 128 pixels end-to-end; records never leave shared memory.
// 512 threads, grid 128.
// ---------------------------------------------------------------------------
__global__ __launch_bounds__(512, 1)
void mega_kernel(const float* __restrict__ x,
                 const float* __restrict__ b_off,
                 const float* __restrict__ bias,
                 float* __restrict__ out)
{
    extern __shared__ char smc[];
    char* sm = smc;
    const int tid = threadIdx.x;
    const int wid = tid >> 5;
    const int lid = tid & 31;
    const int g   = lid >> 2;
    const int t4  = lid & 3;
    const int n0  = blockIdx.x * TN;
    const int b   = n0 >> 12;
    const int hw0 = n0 & 4095;
    const float* xb = x + (size_t)b * CIN * HW;

    ushort4* s_idx = (ushort4*)(sm + REC_BYTE_OFF);
    float4*  s_w   = (float4*) (sm + REC_BYTE_OFF + 9216);

    // ===================== PHASE 1: offset conv GEMM =====================
    {
        const int wm2 = wid & 1;       // M half (16 rows)
        const int wn2 = wid >> 1;      // N sixteenth (16 cols)

        float acc[2][4];
#pragma unroll
        for (int j = 0; j < 2; j++)
#pragma unroll
            for (int q = 0; q < 4; q++) acc[j][q] = 0.f;

        om_fill_A(sm, 0, 0, tid);
        om_fill_B(sm, 0, 0, tid, xb, hw0);

        for (int i = 0; i < KCHUNKS; i++) {
            const int s = i & 1;
            asm volatile("cp.async.wait_group 0;" ::: "memory");
            __syncthreads();

            if (i + 1 < KCHUNKS)
                om_fill_A(sm, s ^ 1, i + 1, tid);

            const uint2* Au2 = (const uint2*)(sm + s * STG2_BYTES);
            const uint2* Bu2 = (const uint2*)(sm + s * STG2_BYTES + A2_BYTES);

#pragma unroll
            for (int q16 = 0; q16 < NQ16; q16++) {
                int m = wm2 * 16 + g;
                uint2 alo = Au2[(q16 * TM2 + m) * 4 + t4];
                uint2 ahi = Au2[(q16 * TM2 + m + 8) * 4 + t4];
                uint2 bb[2];
#pragma unroll
                for (int jj = 0; jj < 2; jj++) {
                    int n = wn2 * 16 + jj * 8 + g;
                    bb[jj] = Bu2[(q16 * TN2 + n) * 4 + ((t4 + (n >> 2)) & 3)];
                }
#pragma unroll
                for (int jj = 0; jj < 2; jj++)
                    mma_f16(acc[jj], alo.x, ahi.x, alo.y, ahi.y,
                            bb[jj].x, bb[jj].y);
            }

            if (i + 1 < KCHUNKS)
                om_fill_B(sm, s ^ 1, i + 1, tid, xb, hw0);
        }

        // Transpose acc -> som[32][128] (reuses phase-1 stage area).
        __syncthreads();
        float* som = (float*)sm;       // 16 KB

        {
            int ra = wm2 * 16 + g;
            int rb = ra + 8;
#pragma unroll
            for (int jj = 0; jj < 2; jj++) {
                int col = wn2 * 16 + jj * 8 + 2 * t4;
                *(float2*)&som[ra * TN2 + col] = make_float2(acc[jj][0], acc[jj][1]);
                *(float2*)&som[rb * TN2 + col] = make_float2(acc[jj][2], acc[jj][3]);
            }
        }
        __syncthreads();

        // Record build: one thread per pixel, results straight into smem.
        if (tid < TN) {
            const int hw = hw0 + tid;
            const int y  = hw >> 6;
            const int xw = hw & 63;

            float a[NOFF];
#pragma unroll
            for (int oc = 0; oc < NOFF; oc++)
                a[oc] = b_off[oc] + som[oc * TN2 + tid];

#pragma unroll
            for (int kp = 0; kp < KKPOS; kp++) {
                float dy = a[2 * kp];
                float dx = a[2 * kp + 1];
                float mask = 1.f / (1.f + __expf(-a[18 + kp]));

                float py = (float)(y  - 1 + kp / 3) + dy;
                float px = (float)(xw - 1 + kp % 3) + dx;
                float y0f = floorf(py), x0f = floorf(px);
                float ly = py - y0f,   lx = px - x0f;
                int y0 = (int)y0f, x0 = (int)x0f;

                ushort4 idx; float4 wv;
                {
                    int yy = y0, xx = x0;
                    bool ok = (yy >= 0 && yy < HDIM && xx >= 0 && xx < WDIM);
                    int yc = min(max(yy, 0), HDIM - 1), xc = min(max(xx, 0), WDIM - 1);
                    idx.x = (unsigned short)(yc * WDIM + xc);
                    wv.x = ok ? (1.f - ly) * (1.f - lx) * mask : 0.f;
                }
                {
                    int yy = y0, xx = x0 + 1;
                    bool ok = (yy >= 0 && yy < HDIM && xx >= 0 && xx < WDIM);
                    int yc = min(max(yy, 0), HDIM - 1), xc = min(max(xx, 0), WDIM - 1);
                    idx.y = (unsigned short)(yc * WDIM + xc);
                    wv.y = ok ? (1.f - ly) * lx * mask : 0.f;
                }
                {
                    int yy = y0 + 1, xx = x0;
                    bool ok = (yy >= 0 && yy < HDIM && xx >= 0 && xx < WDIM);
                    int yc = min(max(yy, 0), HDIM - 1), xc = min(max(xx, 0), WDIM - 1);
                    idx.z = (unsigned short)(yc * WDIM + xc);
                    wv.z = ok ? ly * (1.f - lx) * mask : 0.f;
                }
                {
                    int yy = y0 + 1, xx = x0 + 1;
                    bool ok = (yy >= 0 && yy < HDIM && xx >= 0 && xx < WDIM);
                    int yc = min(max(yy, 0), HDIM - 1), xc = min(max(xx, 0), WDIM - 1);
                    idx.w = (unsigned short)(yc * WDIM + xc);
                    wv.w = ok ? ly * lx * mask : 0.f;
                }

                s_idx[kp * TN + tid] = idx;
                s_w[kp * TN + tid]   = wv;
            }
        }
    }
    __syncthreads();   // records visible to all; phase-1 smem dead

    // ===================== PHASE 2: main GEMM =====================
    const int wm = wid & 3;
    const int wn = wid >> 2;

    float acc[4][4][4];
#pragma unroll
    for (int i = 0; i < 4; i++)
#pragma unroll
        for (int j = 0; j < 4; j++)
#pragma unroll
            for (int q = 0; q < 4; q++) acc[i][j][q] = 0.f;

    fill_A(sm, 0, 0, tid);
    fill_B(sm, 0, 0, tid, xb, s_idx, s_w);

    for (int i = 0; i < KCHUNKS; i++) {
        const int s = i & 1;
        asm volatile("cp.async.wait_group 0;" ::: "memory");
        __syncthreads();   // publishes B(i), frees stage s^1

        if (i + 1 < KCHUNKS)
            fill_A(sm, s ^ 1, i + 1, tid);

        const uint2* Au2 = (const uint2*)(sm + s * STAGE_BYTES);
        const uint2* Bu2 = (const uint2*)(sm + s * STAGE_BYTES + A_BYTES);

#pragma unroll
        for (int q16 = 0; q16 < NQ16; q16++) {
            uint2 alo[4], ahi[4], bb[4];
#pragma unroll
            for (int ii = 0; ii < 4; ii++) {
                int m = wm * 64 + ii * 16 + g;
                alo[ii] = Au2[(q16 * TM + m) * 4 + t4];
                ahi[ii] = Au2[(q16 * TM + m + 8) * 4 + t4];
            }
#pragma unroll
            for (int jj = 0; jj < 4; jj++) {
                int n = wn * 32 + jj * 8 + g;
                bb[jj] = Bu2[(q16 * TN + n) * 4 + ((t4 + (n >> 2)) & 3)];
            }
#pragma unroll
            for (int ii = 0; ii < 4; ii++)
#pragma unroll
                for (int jj = 0; jj < 4; jj++)
                    mma_f16(acc[ii][jj],
                            alo[ii].x, ahi[ii].x, alo[ii].y, ahi[ii].y,
                            bb[jj].x, bb[jj].y);
        }

        if (i + 1 < KCHUNKS)
            fill_B(sm, s ^ 1, i + 1, tid, xb, s_idx, s_w);
    }

    // Epilogue: add bias, store.
#pragma unroll
    for (int ii = 0; ii < 4; ii++) {
        int r0 = wm * 64 + ii * 16 + g;
        float bi0 = bias[r0], bi1 = bias[r0 + 8];
        float* p0 = out + ((size_t)(b * OUTC + r0)) * HW + hw0;
        float* p1 = p0 + (size_t)8 * HW;
#pragma unroll
        for (int jj = 0; jj < 4; jj++) {
            int col = wn * 32 + jj * 8 + 2 * t4;
            float2 v0 = make_float2(acc[ii][jj][0] + bi0, acc[ii][jj][1] + bi0);
            float2 v1 = make_float2(acc[ii][jj][2] + bi1, acc[ii][jj][3] + bi1);
            *(float2*)(p0 + col) = v0;
            *(float2*)(p1 + col) = v1;
        }
    }
}

// ---------------------------------------------------------------------------
// Launch: inputs per metadata order: x, w_off, b_off, weight, bias
// ---------------------------------------------------------------------------
extern "C" void kernel_launch(void* const* d_in, const int* in_sizes, int n_in,
                              void* d_out, int out_size)
{
    const float* x      = (const float*)d_in[0];
    const float* w_off  = (const float*)d_in[1];
    const float* b_off  = (const float*)d_in[2];
    const float* weight = (const float*)d_in[3];
    const float* bias   = (const float*)d_in[4];
    float* out = (float*)d_out;

    cudaFuncSetAttribute(mega_kernel,
                         cudaFuncAttributeMaxDynamicSharedMemorySize,
                         MEGA_SMEM_BYTES);

    wprep_kernel<<<(WMAIN_ELEMS + WOFF_ELEMS + 255) / 256, 256>>>(weight, w_off);

    mega_kernel<<<NPIX / TN, 512, MEGA_SMEM_BYTES>>>(x, b_off, bias, out);
}